// round 2
// baseline (speedup 1.0000x reference)
#include <cuda_runtime.h>
#include <cstdint>

#define NN 100000
#define EE 1600000
#define DD 256
#define SCAN_B 1024
#define NBLK ((NN + SCAN_B - 1) / SCAN_B)   // 98

// ---------------- scratch (device globals; no allocations allowed) ----------
__device__ float g_agg[(size_t)NN * DD];     // aggregation output (mean)
__device__ float g_h[(size_t)NN * DD];       // layer-1 hidden
__device__ int   g_src[EE];
__device__ int   g_dst[EE];
__device__ int   g_is64;
__device__ int   g_deg[NN];
__device__ int   g_scan[NN];
__device__ int   g_rowptr[NN + 1];
__device__ int   g_cursor[NN];
__device__ int   g_csr_src[EE];
__device__ int   g_bsum[NBLK];
__device__ int   g_boff[NBLK];
__device__ float g_W1[DD * DD];              // Wr1 + Wlin1
__device__ float g_W2[DD * DD];              // Wr2 + Wlin2
__device__ float g_b1[DD];
__device__ float g_b2[DD];

// ---------------- edge dtype detection + extraction -------------------------
// If edge_index is int64 (little-endian, values in [0,1e5)), every odd 32-bit
// word is a zero high-half. If int32, odd words are random edge indices.
__global__ void detect_dtype(const int* __restrict__ w) {
    __shared__ int nz;
    if (threadIdx.x == 0) nz = 0;
    __syncthreads();
    int v = w[2 * threadIdx.x + 1];           // odd positions 1,3,...,2047
    if (v != 0) atomicOr(&nz, 1);
    __syncthreads();
    if (threadIdx.x == 0) g_is64 = (nz == 0) ? 1 : 0;
}

__global__ void extract_edges(const int* __restrict__ w) {
    int e = blockIdx.x * blockDim.x + threadIdx.x;
    if (e >= EE) return;
    int is64 = g_is64;
    int s, d;
    if (is64) {
        s = w[2 * (size_t)e];                 // low half of src[e]
        d = w[2 * ((size_t)EE + e)];          // low half of dst[e]
    } else {
        s = w[e];
        d = w[EE + e];
    }
    // defensive clamp (data is in-range; protects against layout surprises)
    s = min(max(s, 0), NN - 1);
    d = min(max(d, 0), NN - 1);
    g_src[e] = s;
    g_dst[e] = d;
}

// ---------------- small prep kernels ----------------------------------------
__global__ void prep_weights(const float* __restrict__ Wr1, const float* __restrict__ Wlin1,
                             const float* __restrict__ b1,  const float* __restrict__ blin1,
                             const float* __restrict__ Wr2, const float* __restrict__ Wlin2,
                             const float* __restrict__ b2,  const float* __restrict__ blin2) {
    int i = blockIdx.x * blockDim.x + threadIdx.x;
    if (i < DD * DD) {
        g_W1[i] = Wr1[i] + Wlin1[i];
        g_W2[i] = Wr2[i] + Wlin2[i];
    }
    if (i < DD) {
        g_b1[i] = b1[i] + blin1[i];
        g_b2[i] = b2[i] + blin2[i];
    }
}

__global__ void zero_counts() {
    int i = blockIdx.x * blockDim.x + threadIdx.x;
    if (i < NN) { g_deg[i] = 0; g_cursor[i] = 0; }
}

__global__ void hist_kernel() {
    int e = blockIdx.x * blockDim.x + threadIdx.x;
    if (e < EE) atomicAdd(&g_deg[g_dst[e]], 1);
}

// ---------------- prefix scan (rowptr) --------------------------------------
__global__ void scanA() {
    __shared__ int sh[SCAN_B];
    int i = blockIdx.x * SCAN_B + threadIdx.x;
    sh[threadIdx.x] = (i < NN) ? g_deg[i] : 0;
    __syncthreads();
    for (int off = 1; off < SCAN_B; off <<= 1) {
        int t = (threadIdx.x >= off) ? sh[threadIdx.x - off] : 0;
        __syncthreads();
        sh[threadIdx.x] += t;
        __syncthreads();
    }
    if (i < NN) g_scan[i] = sh[threadIdx.x];
    if (threadIdx.x == SCAN_B - 1) g_bsum[blockIdx.x] = sh[SCAN_B - 1];
}

__global__ void scanB() {
    if (threadIdx.x == 0 && blockIdx.x == 0) {
        int run = 0;
        for (int b = 0; b < NBLK; b++) { int t = g_bsum[b]; g_boff[b] = run; run += t; }
    }
}

__global__ void scanC() {
    int i = blockIdx.x * blockDim.x + threadIdx.x;
    if (i < NN) g_rowptr[i] = g_scan[i] - g_deg[i] + g_boff[i / SCAN_B];
    if (i == 0) g_rowptr[NN] = EE;
}

__global__ void fill_csr() {
    int e = blockIdx.x * blockDim.x + threadIdx.x;
    if (e < EE) {
        int d = g_dst[e];
        int pos = g_rowptr[d] + atomicAdd(&g_cursor[d], 1);
        g_csr_src[pos] = g_src[e];
    }
}

// ---------------- mean aggregation: one block per dst node ------------------
__global__ void aggregate_kernel(const float* __restrict__ feat, float* __restrict__ out) {
    int row = blockIdx.x;
    int tid = threadIdx.x;
    int start = g_rowptr[row];
    int end   = g_rowptr[row + 1];
    __shared__ int sidx[256];
    float acc = 0.f;
    for (int base = start; base < end; base += 256) {
        int j = base + tid;
        sidx[tid] = (j < end) ? g_csr_src[j] : 0;
        __syncthreads();
        int cnt = min(256, end - base);
        for (int t = 0; t < cnt; t++) {
            acc += feat[(size_t)sidx[t] * DD + tid];
        }
        __syncthreads();
    }
    float scale = (end > start) ? (1.f / (float)(end - start)) : 0.f;
    out[(size_t)row * DD + tid] = acc * scale;
}

// ---------------- fused double GEMM: C = A1@B1 + A2@B2 + bias (opt relu) ----
// A1, A2: [M x 256] row-major.  B1, B2: [256 x 256] row-major.  C: [M x 256].
#define BM 64
#define BN 64
#define BK 16

template <int DO_RELU>
__global__ void __launch_bounds__(256) gemm2x_kernel(
    const float* __restrict__ A1, const float* __restrict__ A2,
    const float* __restrict__ B1, const float* __restrict__ B2,
    const float* __restrict__ bias, float* __restrict__ C, int M) {
    __shared__ float As[BK][BM + 4];
    __shared__ float Bs[BK][BN];

    int tx = threadIdx.x % 16;
    int ty = threadIdx.x / 16;
    int rowBase = blockIdx.x * BM;
    int colBase = blockIdx.y * BN;

    float acc[4][4];
#pragma unroll
    for (int i = 0; i < 4; i++)
#pragma unroll
        for (int j = 0; j < 4; j++) acc[i][j] = 0.f;

    // A-tile load indices
    int ar = threadIdx.x / 4;            // 0..63  (row within tile)
    int ak = (threadIdx.x % 4) * 4;      // 0,4,8,12
    int grow = rowBase + ar; if (grow > M - 1) grow = M - 1;
    // B-tile load indices
    int bk = threadIdx.x / 16;           // 0..15
    int bn = (threadIdx.x % 16) * 4;

#pragma unroll
    for (int op = 0; op < 2; op++) {
        const float* A = op ? A2 : A1;
        const float* B = op ? B2 : B1;
        for (int kk = 0; kk < DD; kk += BK) {
            float4 av = *(const float4*)&A[(size_t)grow * DD + kk + ak];
            As[ak + 0][ar] = av.x;
            As[ak + 1][ar] = av.y;
            As[ak + 2][ar] = av.z;
            As[ak + 3][ar] = av.w;
            float4 bv = *(const float4*)&B[(size_t)(kk + bk) * DD + colBase + bn];
            *(float4*)&Bs[bk][bn] = bv;
            __syncthreads();
#pragma unroll
            for (int k = 0; k < BK; k++) {
                float a0 = As[k][ty * 4 + 0];
                float a1 = As[k][ty * 4 + 1];
                float a2 = As[k][ty * 4 + 2];
                float a3 = As[k][ty * 4 + 3];
                float4 b4 = *(const float4*)&Bs[k][tx * 4];
                acc[0][0] += a0 * b4.x; acc[0][1] += a0 * b4.y; acc[0][2] += a0 * b4.z; acc[0][3] += a0 * b4.w;
                acc[1][0] += a1 * b4.x; acc[1][1] += a1 * b4.y; acc[1][2] += a1 * b4.z; acc[1][3] += a1 * b4.w;
                acc[2][0] += a2 * b4.x; acc[2][1] += a2 * b4.y; acc[2][2] += a2 * b4.z; acc[2][3] += a2 * b4.w;
                acc[3][0] += a3 * b4.x; acc[3][1] += a3 * b4.y; acc[3][2] += a3 * b4.z; acc[3][3] += a3 * b4.w;
            }
            __syncthreads();
        }
    }

    float4 bb = *(const float4*)&bias[colBase + tx * 4];
#pragma unroll
    for (int i = 0; i < 4; i++) {
        int r = rowBase + ty * 4 + i;
        if (r < M) {
            float4 v;
            v.x = acc[i][0] + bb.x;
            v.y = acc[i][1] + bb.y;
            v.z = acc[i][2] + bb.z;
            v.w = acc[i][3] + bb.w;
            if (DO_RELU) {
                v.x = fmaxf(v.x, 0.f); v.y = fmaxf(v.y, 0.f);
                v.z = fmaxf(v.z, 0.f); v.w = fmaxf(v.w, 0.f);
            }
            *(float4*)&C[(size_t)r * DD + colBase + tx * 4] = v;
        }
    }
}

// ---------------- launch -----------------------------------------------------
extern "C" void kernel_launch(void* const* d_in, const int* in_sizes, int n_in,
                              void* d_out, int out_size) {
    const float* x     = (const float*)d_in[0];
    const int*   eidxW = (const int*)d_in[1];   // [2, E], int32 or int64 (auto-detected)
    const float* Wl1   = (const float*)d_in[2];
    const float* Wr1   = (const float*)d_in[3];
    const float* b1    = (const float*)d_in[4];
    const float* Wlin1 = (const float*)d_in[5];
    const float* blin1 = (const float*)d_in[6];
    const float* Wl2   = (const float*)d_in[7];
    const float* Wr2   = (const float*)d_in[8];
    const float* b2    = (const float*)d_in[9];
    const float* Wlin2 = (const float*)d_in[10];
    const float* blin2 = (const float*)d_in[11];
    float* out = (float*)d_out;

    float* agg; cudaGetSymbolAddress((void**)&agg, g_agg);
    float* h;   cudaGetSymbolAddress((void**)&h,   g_h);
    float* W1c; cudaGetSymbolAddress((void**)&W1c, g_W1);
    float* W2c; cudaGetSymbolAddress((void**)&W2c, g_W2);
    float* b1c; cudaGetSymbolAddress((void**)&b1c, g_b1);
    float* b2c; cudaGetSymbolAddress((void**)&b2c, g_b2);

    // 0) decode edge index (dtype-agnostic)
    detect_dtype<<<1, 1024>>>(eidxW);
    extract_edges<<<(EE + 255) / 256, 256>>>(eidxW);

    // 1) combine parallel-linear weights into SAGE root weights
    prep_weights<<<(DD * DD + 255) / 256, 256>>>(Wr1, Wlin1, b1, blin1, Wr2, Wlin2, b2, blin2);

    // 2) build CSR (by dst) once; degree is identical for both layers
    zero_counts<<<(NN + 255) / 256, 256>>>();
    hist_kernel<<<(EE + 255) / 256, 256>>>();
    scanA<<<NBLK, SCAN_B>>>();
    scanB<<<1, 32>>>();
    scanC<<<(NN + 255) / 256, 256>>>();
    fill_csr<<<(EE + 255) / 256, 256>>>();

    dim3 gemmGrid((NN + BM - 1) / BM, DD / BN);

    // 3) layer 1
    aggregate_kernel<<<NN, 256>>>(x, agg);
    gemm2x_kernel<1><<<gemmGrid, 256>>>(agg, x, Wl1, W1c, b1c, h, NN);

    // 4) layer 2
    aggregate_kernel<<<NN, 256>>>(h, agg);
    gemm2x_kernel<0><<<gemmGrid, 256>>>(agg, h, Wl2, W2c, b2c, out, NN);
}

// round 3
// speedup vs baseline: 1.1285x; 1.1285x over previous
#include <cuda_runtime.h>
#include <cuda_bf16.h>
#include <cstdint>

#define NN 100000
#define EE 1600000
#define DD 256
#define SCAN_B 1024
#define NBLK ((NN + SCAN_B - 1) / SCAN_B)   // 98

// ---------------- scratch (device globals; no allocations allowed) ----------
__device__ __nv_bfloat16 g_xh[(size_t)NN * DD];
__device__ __nv_bfloat16 g_xl[(size_t)NN * DD];
__device__ __nv_bfloat16 g_aggh[(size_t)NN * DD];
__device__ __nv_bfloat16 g_aggl[(size_t)NN * DD];
__device__ __nv_bfloat16 g_hh[(size_t)NN * DD];
__device__ __nv_bfloat16 g_hl[(size_t)NN * DD];
__device__ float g_h[(size_t)NN * DD];       // layer-1 hidden fp32 (for aggregation 2)
__device__ int   g_src[EE];
__device__ int   g_dst[EE];
__device__ int   g_is64;
__device__ int   g_deg[NN];
__device__ int   g_scan[NN];
__device__ int   g_rowptr[NN + 1];
__device__ int   g_cursor[NN];
__device__ int   g_csr_src[EE];
__device__ int   g_bsum[NBLK];
__device__ int   g_boff[NBLK];
__device__ float g_W1[DD * DD];              // Wr1 + Wlin1 (fp32 combined)
__device__ float g_W2[DD * DD];              // Wr2 + Wlin2
__device__ float g_b1[DD];
__device__ float g_b2[DD];
// transposed + split B matrices: layout [n][k] (n-major), bf16
__device__ __nv_bfloat16 g_B1h[DD * DD], g_B1l[DD * DD];   // Wl1
__device__ __nv_bfloat16 g_B2h[DD * DD], g_B2l[DD * DD];   // Wr1+Wlin1
__device__ __nv_bfloat16 g_B3h[DD * DD], g_B3l[DD * DD];   // Wl2
__device__ __nv_bfloat16 g_B4h[DD * DD], g_B4l[DD * DD];   // Wr2+Wlin2

// ---------------- PTX helpers ------------------------------------------------
__device__ __forceinline__ void mma_bf16(float* d, const uint32_t* a, const uint32_t* b) {
    asm volatile(
        "mma.sync.aligned.m16n8k16.row.col.f32.bf16.bf16.f32 "
        "{%0,%1,%2,%3}, {%4,%5,%6,%7}, {%8,%9}, {%0,%1,%2,%3};\n"
        : "+f"(d[0]), "+f"(d[1]), "+f"(d[2]), "+f"(d[3])
        : "r"(a[0]), "r"(a[1]), "r"(a[2]), "r"(a[3]), "r"(b[0]), "r"(b[1]));
}

__device__ __forceinline__ void cp_async16(uint32_t saddr, const void* gaddr) {
    asm volatile("cp.async.cg.shared.global [%0], [%1], 16;\n" :: "r"(saddr), "l"(gaddr));
}

__device__ __forceinline__ uint32_t smem_u32(const void* p) {
    return (uint32_t)__cvta_generic_to_shared(p);
}

// ---------------- edge dtype detection + extraction -------------------------
__global__ void detect_dtype(const int* __restrict__ w) {
    __shared__ int nz;
    if (threadIdx.x == 0) nz = 0;
    __syncthreads();
    int v = w[2 * threadIdx.x + 1];
    if (v != 0) atomicOr(&nz, 1);
    __syncthreads();
    if (threadIdx.x == 0) g_is64 = (nz == 0) ? 1 : 0;
}

__global__ void extract_edges(const int* __restrict__ w) {
    int e = blockIdx.x * blockDim.x + threadIdx.x;
    if (e >= EE) return;
    int s, d;
    if (g_is64) {
        s = w[2 * (size_t)e];
        d = w[2 * ((size_t)EE + e)];
    } else {
        s = w[e];
        d = w[EE + e];
    }
    s = min(max(s, 0), NN - 1);
    d = min(max(d, 0), NN - 1);
    g_src[e] = s;
    g_dst[e] = d;
}

// ---------------- prep: combine weights, split+transpose --------------------
__global__ void prep_weights(const float* __restrict__ Wr1, const float* __restrict__ Wlin1,
                             const float* __restrict__ b1,  const float* __restrict__ blin1,
                             const float* __restrict__ Wr2, const float* __restrict__ Wlin2,
                             const float* __restrict__ b2,  const float* __restrict__ blin2) {
    int i = blockIdx.x * blockDim.x + threadIdx.x;
    if (i < DD * DD) {
        g_W1[i] = Wr1[i] + Wlin1[i];
        g_W2[i] = Wr2[i] + Wlin2[i];
    }
    if (i < DD) {
        g_b1[i] = b1[i] + blin1[i];
        g_b2[i] = b2[i] + blin2[i];
    }
}

// transpose [k][n] -> [n][k], split into hi/lo bf16. blockIdx.x = k row,
// blockIdx.y selects matrix, threadIdx.x = n.
__global__ void transpose_split(const float* __restrict__ Wl1, const float* __restrict__ Wl2) {
    int k = blockIdx.x, n = threadIdx.x;
    const float* src;
    __nv_bfloat16 *dh, *dl;
    switch (blockIdx.y) {
        case 0:  src = Wl1;  dh = g_B1h; dl = g_B1l; break;
        case 1:  src = g_W1; dh = g_B2h; dl = g_B2l; break;
        case 2:  src = Wl2;  dh = g_B3h; dl = g_B3l; break;
        default: src = g_W2; dh = g_B4h; dl = g_B4l; break;
    }
    float v = src[k * DD + n];
    __nv_bfloat16 hi = __float2bfloat16(v);
    float lo = v - __bfloat162float(hi);
    dh[n * DD + k] = hi;
    dl[n * DD + k] = __float2bfloat16(lo);
}

// split x (fp32) into hi/lo bf16
__global__ void split_x(const float* __restrict__ x) {
    size_t i = (size_t)blockIdx.x * blockDim.x + threadIdx.x;
    if (i >= (size_t)NN * DD) return;
    float v = x[i];
    __nv_bfloat16 hi = __float2bfloat16(v);
    float lo = v - __bfloat162float(hi);
    g_xh[i] = hi;
    g_xl[i] = __float2bfloat16(lo);
}

// ---------------- CSR build --------------------------------------------------
__global__ void zero_counts() {
    int i = blockIdx.x * blockDim.x + threadIdx.x;
    if (i < NN) { g_deg[i] = 0; g_cursor[i] = 0; }
}

__global__ void hist_kernel() {
    int e = blockIdx.x * blockDim.x + threadIdx.x;
    if (e < EE) atomicAdd(&g_deg[g_dst[e]], 1);
}

__global__ void scanA() {
    __shared__ int sh[SCAN_B];
    int i = blockIdx.x * SCAN_B + threadIdx.x;
    sh[threadIdx.x] = (i < NN) ? g_deg[i] : 0;
    __syncthreads();
    for (int off = 1; off < SCAN_B; off <<= 1) {
        int t = (threadIdx.x >= off) ? sh[threadIdx.x - off] : 0;
        __syncthreads();
        sh[threadIdx.x] += t;
        __syncthreads();
    }
    if (i < NN) g_scan[i] = sh[threadIdx.x];
    if (threadIdx.x == SCAN_B - 1) g_bsum[blockIdx.x] = sh[SCAN_B - 1];
}

__global__ void scanB() {
    if (threadIdx.x == 0 && blockIdx.x == 0) {
        int run = 0;
        for (int b = 0; b < NBLK; b++) { int t = g_bsum[b]; g_boff[b] = run; run += t; }
    }
}

__global__ void scanC() {
    int i = blockIdx.x * blockDim.x + threadIdx.x;
    if (i < NN) g_rowptr[i] = g_scan[i] - g_deg[i] + g_boff[i / SCAN_B];
    if (i == 0) g_rowptr[NN] = EE;
}

__global__ void fill_csr() {
    int e = blockIdx.x * blockDim.x + threadIdx.x;
    if (e < EE) {
        int d = g_dst[e];
        int pos = g_rowptr[d] + atomicAdd(&g_cursor[d], 1);
        g_csr_src[pos] = g_src[e];
    }
}

// ---------------- mean aggregation: one block per dst node ------------------
// writes mean directly as split bf16 (hi/lo)
__global__ void aggregate_split(const float* __restrict__ feat,
                                __nv_bfloat16* __restrict__ oh,
                                __nv_bfloat16* __restrict__ ol) {
    int row = blockIdx.x;
    int tid = threadIdx.x;
    int start = g_rowptr[row];
    int end   = g_rowptr[row + 1];
    __shared__ int sidx[256];
    float acc = 0.f;
    for (int base = start; base < end; base += 256) {
        int j = base + tid;
        sidx[tid] = (j < end) ? g_csr_src[j] : 0;
        __syncthreads();
        int cnt = min(256, end - base);
        for (int t = 0; t < cnt; t++) {
            acc += feat[(size_t)sidx[t] * DD + tid];
        }
        __syncthreads();
    }
    float scale = (end > start) ? (1.f / (float)(end - start)) : 0.f;
    float v = acc * scale;
    __nv_bfloat16 hi = __float2bfloat16(v);
    float lo = v - __bfloat162float(hi);
    oh[(size_t)row * DD + tid] = hi;
    ol[(size_t)row * DD + tid] = __float2bfloat16(lo);
}

// ---------------- split-bf16 double GEMM via tensor cores -------------------
// C = A1@B1 + A2@B2 + bias, with each product computed as
//   Ahi@Bhi + Ahi@Blo + Alo@Bhi    (bf16 inputs, fp32 accumulate)
// A*: [M x 256] row-major bf16.  B*: [256 n][256 k] n-major (pre-transposed) bf16.
// Block tile 128x128, 8 warps (warp tile 32x64), BK=32, double-buffered cp.async.
#define G_BM 128
#define G_BN 128
#define G_BK 32
#define NSTAGES 48           // 6 segments * (256/32)

template <int RELU, int SPLIT>
__global__ void __launch_bounds__(256, 2) gemm_mma(
    const __nv_bfloat16* __restrict__ A1h, const __nv_bfloat16* __restrict__ A1l,
    const __nv_bfloat16* __restrict__ A2h, const __nv_bfloat16* __restrict__ A2l,
    const __nv_bfloat16* __restrict__ B1h, const __nv_bfloat16* __restrict__ B1l,
    const __nv_bfloat16* __restrict__ B2h, const __nv_bfloat16* __restrict__ B2l,
    const float* __restrict__ bias,
    float* __restrict__ Cf, __nv_bfloat16* __restrict__ Ch, __nv_bfloat16* __restrict__ Cl,
    int M)
{
    __shared__ __nv_bfloat16 As[2][G_BM][G_BK];
    __shared__ __nv_bfloat16 Bs[2][G_BN][G_BK];

    const int tid  = threadIdx.x;
    const int wid  = tid >> 5;
    const int lane = tid & 31;
    const int grp  = lane >> 2;      // 0..7
    const int tig  = lane & 3;       // 0..3
    const int wm   = (wid & 3) * 32; // warp M offset (4 warps)
    const int wn   = (wid >> 2) * 64;// warp N offset (2 warps)
    const int rowBase = blockIdx.x * G_BM;
    const int colBase = blockIdx.y * G_BN;

    const __nv_bfloat16* Aseg[6] = {A1h, A1h, A1l, A2h, A2h, A2l};
    const __nv_bfloat16* Bseg[6] = {B1h, B1l, B1h, B2h, B2l, B2h};

    float acc[2][8][4];
#pragma unroll
    for (int mi = 0; mi < 2; mi++)
#pragma unroll
        for (int nj = 0; nj < 8; nj++)
#pragma unroll
            for (int c = 0; c < 4; c++) acc[mi][nj][c] = 0.f;

    // global->smem tile loaders: each thread copies 4x16B per stage
    const int r0 = tid >> 2;         // 0..63
    const int q  = (tid & 3) * 8;    // bf16 col offset within BK=32
    const size_t ga0 = (size_t)min(rowBase + r0, M - 1) * DD;
    const size_t ga1 = (size_t)min(rowBase + r0 + 64, M - 1) * DD;
    const size_t gb0 = (size_t)(colBase + r0) * DD;
    const size_t gb1 = (size_t)(colBase + r0 + 64) * DD;

    auto load_stage = [&](int stage, int buf) {
        const int s  = stage >> 3;
        const int kk = (stage & 7) * G_BK;
        const __nv_bfloat16* A = Aseg[s];
        const __nv_bfloat16* B = Bseg[s];
        cp_async16(smem_u32(&As[buf][r0][q]),      A + ga0 + kk + q);
        cp_async16(smem_u32(&As[buf][r0 + 64][q]), A + ga1 + kk + q);
        cp_async16(smem_u32(&Bs[buf][r0][q]),      B + gb0 + kk + q);
        cp_async16(smem_u32(&Bs[buf][r0 + 64][q]), B + gb1 + kk + q);
    };

    load_stage(0, 0);
    asm volatile("cp.async.commit_group;\n");

    for (int stage = 0; stage < NSTAGES; ++stage) {
        const int buf = stage & 1;
        if (stage + 1 < NSTAGES) {
            load_stage(stage + 1, buf ^ 1);
            asm volatile("cp.async.commit_group;\n");
            asm volatile("cp.async.wait_group 1;\n");
        } else {
            asm volatile("cp.async.wait_group 0;\n");
        }
        __syncthreads();

        const uint32_t* As32 = (const uint32_t*)&As[buf][0][0];  // [128][16] words
        const uint32_t* Bs32 = (const uint32_t*)&Bs[buf][0][0];  // [128][16] words

#pragma unroll
        for (int ks = 0; ks < 2; ++ks) {
            const int kw = ks * 8 + tig;   // word column (k/2)
            uint32_t af[2][4], bfr[8][2];
#pragma unroll
            for (int mi = 0; mi < 2; ++mi) {
                const int r = wm + mi * 16 + grp;
                af[mi][0] = As32[r * 16 + kw];
                af[mi][1] = As32[(r + 8) * 16 + kw];
                af[mi][2] = As32[r * 16 + kw + 4];
                af[mi][3] = As32[(r + 8) * 16 + kw + 4];
            }
#pragma unroll
            for (int nj = 0; nj < 8; ++nj) {
                const int n = wn + nj * 8 + grp;
                bfr[nj][0] = Bs32[n * 16 + kw];
                bfr[nj][1] = Bs32[n * 16 + kw + 4];
            }
#pragma unroll
            for (int mi = 0; mi < 2; ++mi)
#pragma unroll
                for (int nj = 0; nj < 8; ++nj)
                    mma_bf16(acc[mi][nj], af[mi], bfr[nj]);
        }
        __syncthreads();
    }

    // epilogue
#pragma unroll
    for (int mi = 0; mi < 2; ++mi) {
        const int rA = rowBase + wm + mi * 16 + grp;
#pragma unroll
        for (int nj = 0; nj < 8; ++nj) {
            const int col = colBase + wn + nj * 8 + tig * 2;
            const float bb0 = bias[col], bb1 = bias[col + 1];
            float v0 = acc[mi][nj][0] + bb0;
            float v1 = acc[mi][nj][1] + bb1;
            float v2 = acc[mi][nj][2] + bb0;
            float v3 = acc[mi][nj][3] + bb1;
            if (RELU) {
                v0 = fmaxf(v0, 0.f); v1 = fmaxf(v1, 0.f);
                v2 = fmaxf(v2, 0.f); v3 = fmaxf(v3, 0.f);
            }
            if (rA < M) {
                *(float2*)&Cf[(size_t)rA * DD + col] = make_float2(v0, v1);
                if (SPLIT) {
                    __nv_bfloat16 h0 = __float2bfloat16(v0), h1 = __float2bfloat16(v1);
                    __nv_bfloat162 hp; hp.x = h0; hp.y = h1;
                    __nv_bfloat162 lp;
                    lp.x = __float2bfloat16(v0 - __bfloat162float(h0));
                    lp.y = __float2bfloat16(v1 - __bfloat162float(h1));
                    *(__nv_bfloat162*)&Ch[(size_t)rA * DD + col] = hp;
                    *(__nv_bfloat162*)&Cl[(size_t)rA * DD + col] = lp;
                }
            }
            if (rA + 8 < M) {
                *(float2*)&Cf[(size_t)(rA + 8) * DD + col] = make_float2(v2, v3);
                if (SPLIT) {
                    __nv_bfloat16 h2 = __float2bfloat16(v2), h3 = __float2bfloat16(v3);
                    __nv_bfloat162 hp; hp.x = h2; hp.y = h3;
                    __nv_bfloat162 lp;
                    lp.x = __float2bfloat16(v2 - __bfloat162float(h2));
                    lp.y = __float2bfloat16(v3 - __bfloat162float(h3));
                    *(__nv_bfloat162*)&Ch[(size_t)(rA + 8) * DD + col] = hp;
                    *(__nv_bfloat162*)&Cl[(size_t)(rA + 8) * DD + col] = lp;
                }
            }
        }
    }
}

// ---------------- launch -----------------------------------------------------
extern "C" void kernel_launch(void* const* d_in, const int* in_sizes, int n_in,
                              void* d_out, int out_size) {
    const float* x     = (const float*)d_in[0];
    const int*   eidxW = (const int*)d_in[1];   // [2, E], int32 or int64 (auto-detected)
    const float* Wl1   = (const float*)d_in[2];
    const float* Wr1   = (const float*)d_in[3];
    const float* b1    = (const float*)d_in[4];
    const float* Wlin1 = (const float*)d_in[5];
    const float* blin1 = (const float*)d_in[6];
    const float* Wl2   = (const float*)d_in[7];
    const float* Wr2   = (const float*)d_in[8];
    const float* b2    = (const float*)d_in[9];
    const float* Wlin2 = (const float*)d_in[10];
    const float* blin2 = (const float*)d_in[11];
    float* out = (float*)d_out;

    float* h;   cudaGetSymbolAddress((void**)&h,   g_h);
    float* b1c; cudaGetSymbolAddress((void**)&b1c, g_b1);
    float* b2c; cudaGetSymbolAddress((void**)&b2c, g_b2);
    __nv_bfloat16 *xh, *xl, *aggh, *aggl, *hh, *hl;
    cudaGetSymbolAddress((void**)&xh, g_xh);
    cudaGetSymbolAddress((void**)&xl, g_xl);
    cudaGetSymbolAddress((void**)&aggh, g_aggh);
    cudaGetSymbolAddress((void**)&aggl, g_aggl);
    cudaGetSymbolAddress((void**)&hh, g_hh);
    cudaGetSymbolAddress((void**)&hl, g_hl);
    __nv_bfloat16 *B1h, *B1l, *B2h, *B2l, *B3h, *B3l, *B4h, *B4l;
    cudaGetSymbolAddress((void**)&B1h, g_B1h);
    cudaGetSymbolAddress((void**)&B1l, g_B1l);
    cudaGetSymbolAddress((void**)&B2h, g_B2h);
    cudaGetSymbolAddress((void**)&B2l, g_B2l);
    cudaGetSymbolAddress((void**)&B3h, g_B3h);
    cudaGetSymbolAddress((void**)&B3l, g_B3l);
    cudaGetSymbolAddress((void**)&B4h, g_B4h);
    cudaGetSymbolAddress((void**)&B4l, g_B4l);

    // 0) decode edge index (dtype-agnostic)
    detect_dtype<<<1, 1024>>>(eidxW);
    extract_edges<<<(EE + 255) / 256, 256>>>(eidxW);

    // 1) weight prep: combine parallel linear into root, transpose+split to bf16
    prep_weights<<<(DD * DD + 255) / 256, 256>>>(Wr1, Wlin1, b1, blin1, Wr2, Wlin2, b2, blin2);
    transpose_split<<<dim3(DD, 4), DD>>>(Wl1, Wl2);
    split_x<<<(int)(((size_t)NN * DD + 255) / 256), 256>>>(x);

    // 2) build CSR (by dst) once
    zero_counts<<<(NN + 255) / 256, 256>>>();
    hist_kernel<<<(EE + 255) / 256, 256>>>();
    scanA<<<NBLK, SCAN_B>>>();
    scanB<<<1, 32>>>();
    scanC<<<(NN + 255) / 256, 256>>>();
    fill_csr<<<(EE + 255) / 256, 256>>>();

    dim3 gemmGrid((NN + G_BM - 1) / G_BM, DD / G_BN);

    // 3) layer 1
    aggregate_split<<<NN, 256>>>(x, aggh, aggl);
    gemm_mma<1, 1><<<gemmGrid, 256>>>(aggh, aggl, xh, xl,
                                      B1h, B1l, B2h, B2l,
                                      b1c, h, hh, hl, NN);

    // 4) layer 2
    aggregate_split<<<NN, 256>>>(h, aggh, aggl);
    gemm_mma<0, 0><<<gemmGrid, 256>>>(aggh, aggl, hh, hl,
                                      B3h, B3l, B4h, B4l,
                                      b2c, out, nullptr, nullptr, NN);
}

// round 6
// speedup vs baseline: 1.6089x; 1.4258x over previous
#include <cuda_runtime.h>
#include <cuda_bf16.h>
#include <cstdint>

#define NN 100000
#define EE 1600000
#define DD 256
#define SCAN_B 1024
#define NBLK ((NN + SCAN_B - 1) / SCAN_B)   // 98

// ---------------- scratch (device globals; no allocations allowed) ----------
__device__ __nv_bfloat16 g_xh[(size_t)NN * DD];
__device__ __nv_bfloat16 g_xl[(size_t)NN * DD];
__device__ __nv_bfloat16 g_aggh[(size_t)NN * DD];
__device__ __nv_bfloat16 g_aggl[(size_t)NN * DD];
__device__ __nv_bfloat16 g_hh[(size_t)NN * DD];
__device__ __nv_bfloat16 g_hl[(size_t)NN * DD];
__device__ float g_h[(size_t)NN * DD];       // layer-1 hidden fp32 (for aggregation 2)
__device__ int   g_src[EE];
__device__ int   g_dst[EE];
__device__ int   g_is64;
__device__ int   g_deg[NN];
__device__ int   g_scan[NN];
__device__ int   g_rowptr[NN + 1];
__device__ int   g_cursor[NN];
__device__ int   g_csr_src[EE];
__device__ int   g_bsum[NBLK];
__device__ int   g_boff[NBLK];
__device__ float g_W1[DD * DD];              // Wr1 + Wlin1 (fp32 combined)
__device__ float g_W2[DD * DD];              // Wr2 + Wlin2
__device__ float g_b1[DD];
__device__ float g_b2[DD];
// transposed + split B matrices: layout [n][k] (n-major), bf16
__device__ __nv_bfloat16 g_B1h[DD * DD], g_B1l[DD * DD];   // Wl1
__device__ __nv_bfloat16 g_B2h[DD * DD], g_B2l[DD * DD];   // Wr1+Wlin1
__device__ __nv_bfloat16 g_B3h[DD * DD], g_B3l[DD * DD];   // Wl2
__device__ __nv_bfloat16 g_B4h[DD * DD], g_B4l[DD * DD];   // Wr2+Wlin2

// ---------------- PTX helpers ------------------------------------------------
__device__ __forceinline__ void mma_bf16(float* d, const uint32_t* a, const uint32_t* b) {
    asm volatile(
        "mma.sync.aligned.m16n8k16.row.col.f32.bf16.bf16.f32 "
        "{%0,%1,%2,%3}, {%4,%5,%6,%7}, {%8,%9}, {%0,%1,%2,%3};\n"
        : "+f"(d[0]), "+f"(d[1]), "+f"(d[2]), "+f"(d[3])
        : "r"(a[0]), "r"(a[1]), "r"(a[2]), "r"(a[3]), "r"(b[0]), "r"(b[1]));
}

__device__ __forceinline__ void cp_async16(uint32_t saddr, const void* gaddr) {
    asm volatile("cp.async.cg.shared.global [%0], [%1], 16;\n" :: "r"(saddr), "l"(gaddr));
}

__device__ __forceinline__ uint32_t smem_u32(const void* p) {
    return (uint32_t)__cvta_generic_to_shared(p);
}

// ---------------- edge dtype detection + extraction -------------------------
__global__ void detect_dtype(const int* __restrict__ w) {
    __shared__ int nz;
    if (threadIdx.x == 0) nz = 0;
    __syncthreads();
    int v = w[2 * threadIdx.x + 1];
    if (v != 0) atomicOr(&nz, 1);
    __syncthreads();
    if (threadIdx.x == 0) g_is64 = (nz == 0) ? 1 : 0;
}

__global__ void extract_edges(const int* __restrict__ w) {
    int e = blockIdx.x * blockDim.x + threadIdx.x;
    if (e >= EE) return;
    int s, d;
    if (g_is64) {
        s = w[2 * (size_t)e];
        d = w[2 * ((size_t)EE + e)];
    } else {
        s = w[e];
        d = w[EE + e];
    }
    s = min(max(s, 0), NN - 1);
    d = min(max(d, 0), NN - 1);
    g_src[e] = s;
    g_dst[e] = d;
}

// ---------------- prep: combine weights, split+transpose --------------------
__global__ void prep_weights(const float* __restrict__ Wr1, const float* __restrict__ Wlin1,
                             const float* __restrict__ b1,  const float* __restrict__ blin1,
                             const float* __restrict__ Wr2, const float* __restrict__ Wlin2,
                             const float* __restrict__ b2,  const float* __restrict__ blin2) {
    int i = blockIdx.x * blockDim.x + threadIdx.x;
    if (i < DD * DD) {
        g_W1[i] = Wr1[i] + Wlin1[i];
        g_W2[i] = Wr2[i] + Wlin2[i];
    }
    if (i < DD) {
        g_b1[i] = b1[i] + blin1[i];
        g_b2[i] = b2[i] + blin2[i];
    }
}

// transpose [k][n] -> [n][k], split into hi/lo bf16
__global__ void transpose_split(const float* __restrict__ Wl1, const float* __restrict__ Wl2) {
    int k = blockIdx.x, n = threadIdx.x;
    const float* src;
    __nv_bfloat16 *dh, *dl;
    switch (blockIdx.y) {
        case 0:  src = Wl1;  dh = g_B1h; dl = g_B1l; break;
        case 1:  src = g_W1; dh = g_B2h; dl = g_B2l; break;
        case 2:  src = Wl2;  dh = g_B3h; dl = g_B3l; break;
        default: src = g_W2; dh = g_B4h; dl = g_B4l; break;
    }
    float v = src[k * DD + n];
    __nv_bfloat16 hi = __float2bfloat16(v);
    float lo = v - __bfloat162float(hi);
    dh[n * DD + k] = hi;
    dl[n * DD + k] = __float2bfloat16(lo);
}

__global__ void split_x(const float* __restrict__ x) {
    size_t i = (size_t)blockIdx.x * blockDim.x + threadIdx.x;
    if (i >= (size_t)NN * DD) return;
    float v = x[i];
    __nv_bfloat16 hi = __float2bfloat16(v);
    float lo = v - __bfloat162float(hi);
    g_xh[i] = hi;
    g_xl[i] = __float2bfloat16(lo);
}

// ---------------- CSR build --------------------------------------------------
__global__ void zero_counts() {
    int i = blockIdx.x * blockDim.x + threadIdx.x;
    if (i < NN) { g_deg[i] = 0; g_cursor[i] = 0; }
}

__global__ void hist_kernel() {
    int e = blockIdx.x * blockDim.x + threadIdx.x;
    if (e < EE) atomicAdd(&g_deg[g_dst[e]], 1);
}

__global__ void scanA() {
    __shared__ int sh[SCAN_B];
    int i = blockIdx.x * SCAN_B + threadIdx.x;
    sh[threadIdx.x] = (i < NN) ? g_deg[i] : 0;
    __syncthreads();
    for (int off = 1; off < SCAN_B; off <<= 1) {
        int t = (threadIdx.x >= off) ? sh[threadIdx.x - off] : 0;
        __syncthreads();
        sh[threadIdx.x] += t;
        __syncthreads();
    }
    if (i < NN) g_scan[i] = sh[threadIdx.x];
    if (threadIdx.x == SCAN_B - 1) g_bsum[blockIdx.x] = sh[SCAN_B - 1];
}

__global__ void scanB() {
    if (threadIdx.x == 0 && blockIdx.x == 0) {
        int run = 0;
        for (int b = 0; b < NBLK; b++) { int t = g_bsum[b]; g_boff[b] = run; run += t; }
    }
}

__global__ void scanC() {
    int i = blockIdx.x * blockDim.x + threadIdx.x;
    if (i < NN) g_rowptr[i] = g_scan[i] - g_deg[i] + g_boff[i / SCAN_B];
    if (i == 0) g_rowptr[NN] = EE;
}

__global__ void fill_csr() {
    int e = blockIdx.x * blockDim.x + threadIdx.x;
    if (e < EE) {
        int d = g_dst[e];
        int pos = g_rowptr[d] + atomicAdd(&g_cursor[d], 1);
        g_csr_src[pos] = g_src[e];
    }
}

// ---------------- mean aggregation: one block per dst node, MLP=4 -----------
__global__ void aggregate_split(const float* __restrict__ feat,
                                __nv_bfloat16* __restrict__ oh,
                                __nv_bfloat16* __restrict__ ol) {
    int row = blockIdx.x;
    int tid = threadIdx.x;
    int start = g_rowptr[row];
    int end   = g_rowptr[row + 1];
    __shared__ int sidx[256];
    float acc = 0.f;
    for (int base = start; base < end; base += 256) {
        int j = base + tid;
        sidx[tid] = (j < end) ? g_csr_src[j] : 0;
        __syncthreads();
        int cnt = min(256, end - base);
        int t = 0;
        for (; t + 4 <= cnt; t += 4) {
            size_t i0 = (size_t)sidx[t]     * DD;
            size_t i1 = (size_t)sidx[t + 1] * DD;
            size_t i2 = (size_t)sidx[t + 2] * DD;
            size_t i3 = (size_t)sidx[t + 3] * DD;
            float v0 = feat[i0 + tid];
            float v1 = feat[i1 + tid];
            float v2 = feat[i2 + tid];
            float v3 = feat[i3 + tid];
            acc += (v0 + v1) + (v2 + v3);
        }
        for (; t < cnt; t++) acc += feat[(size_t)sidx[t] * DD + tid];
        __syncthreads();
    }
    float scale = (end > start) ? (1.f / (float)(end - start)) : 0.f;
    float v = acc * scale;
    __nv_bfloat16 hi = __float2bfloat16(v);
    float lo = v - __bfloat162float(hi);
    oh[(size_t)row * DD + tid] = hi;
    ol[(size_t)row * DD + tid] = __float2bfloat16(lo);
}

// ---------------- split-bf16 double GEMM via tensor cores -------------------
// C = A1@B1 + A2@B2 + bias, each product as Ahi@Bhi + Ahi@Blo + Alo@Bhi
// A*: [M x 256] row-major bf16.  B*: [256 n][256 k] n-major (pre-transposed) bf16.
// Block tile 128x128, 8 warps (warp tile 32x64), BK=32, double-buffered cp.async.
// Smem padded to word-stride 20 (bf16 stride 40): all fragment LDS and cp.async
// STS patterns are 32-bank conflict-free (banks r*20%32 = {0,20,8,28,16,4,24,12}).
#define G_BM 128
#define G_BN 128
#define G_BK 32
#define PADW 20                 // words per smem row (16 data + 4 pad)
#define NSTAGES 48              // 6 segments * (256/32)

template <int RELU, int SPLIT>
__global__ void __launch_bounds__(256, 2) gemm_mma(
    const __nv_bfloat16* __restrict__ A1h, const __nv_bfloat16* __restrict__ A1l,
    const __nv_bfloat16* __restrict__ A2h, const __nv_bfloat16* __restrict__ A2l,
    const __nv_bfloat16* __restrict__ B1h, const __nv_bfloat16* __restrict__ B1l,
    const __nv_bfloat16* __restrict__ B2h, const __nv_bfloat16* __restrict__ B2l,
    const float* __restrict__ bias,
    float* __restrict__ Cf, __nv_bfloat16* __restrict__ Ch, __nv_bfloat16* __restrict__ Cl,
    int M)
{
    __shared__ __nv_bfloat16 As[2][G_BM][PADW * 2];
    __shared__ __nv_bfloat16 Bs[2][G_BN][PADW * 2];

    const int tid  = threadIdx.x;
    const int wid  = tid >> 5;
    const int lane = tid & 31;
    const int grp  = lane >> 2;      // 0..7
    const int tig  = lane & 3;       // 0..3
    const int wm   = (wid & 3) * 32; // warp M offset (4 warps)
    const int wn   = (wid >> 2) * 64;// warp N offset (2 warps)
    const int rowBase = blockIdx.x * G_BM;
    const int colBase = blockIdx.y * G_BN;

    const __nv_bfloat16* Aseg[6] = {A1h, A1h, A1l, A2h, A2h, A2l};
    const __nv_bfloat16* Bseg[6] = {B1h, B1l, B1h, B2h, B2l, B2h};

    float acc[2][8][4];
#pragma unroll
    for (int mi = 0; mi < 2; mi++)
#pragma unroll
        for (int nj = 0; nj < 8; nj++)
#pragma unroll
            for (int c = 0; c < 4; c++) acc[mi][nj][c] = 0.f;

    // global->smem tile loaders: each thread copies 4x16B per stage
    const int r0 = tid >> 2;         // 0..63
    const int q  = (tid & 3) * 8;    // bf16 col offset within BK=32 (16B chunks)
    const size_t ga0 = (size_t)min(rowBase + r0, M - 1) * DD;
    const size_t ga1 = (size_t)min(rowBase + r0 + 64, M - 1) * DD;
    const size_t gb0 = (size_t)(colBase + r0) * DD;
    const size_t gb1 = (size_t)(colBase + r0 + 64) * DD;

    auto load_stage = [&](int stage, int buf) {
        const int s  = stage >> 3;
        const int kk = (stage & 7) * G_BK;
        const __nv_bfloat16* A = Aseg[s];
        const __nv_bfloat16* B = Bseg[s];
        cp_async16(smem_u32(&As[buf][r0][q]),      A + ga0 + kk + q);
        cp_async16(smem_u32(&As[buf][r0 + 64][q]), A + ga1 + kk + q);
        cp_async16(smem_u32(&Bs[buf][r0][q]),      B + gb0 + kk + q);
        cp_async16(smem_u32(&Bs[buf][r0 + 64][q]), B + gb1 + kk + q);
    };

    load_stage(0, 0);
    asm volatile("cp.async.commit_group;\n");

    for (int stage = 0; stage < NSTAGES; ++stage) {
        const int buf = stage & 1;
        if (stage + 1 < NSTAGES) {
            load_stage(stage + 1, buf ^ 1);
            asm volatile("cp.async.commit_group;\n");
            asm volatile("cp.async.wait_group 1;\n");
        } else {
            asm volatile("cp.async.wait_group 0;\n");
        }
        __syncthreads();

        const uint32_t* As32 = (const uint32_t*)&As[buf][0][0];  // [128][PADW] words
        const uint32_t* Bs32 = (const uint32_t*)&Bs[buf][0][0];

#pragma unroll
        for (int ks = 0; ks < 2; ++ks) {
            const int kw = ks * 8 + tig;   // word column (k/2)
            uint32_t af[2][4], bfr[8][2];
#pragma unroll
            for (int mi = 0; mi < 2; ++mi) {
                const int r = wm + mi * 16 + grp;
                af[mi][0] = As32[r * PADW + kw];
                af[mi][1] = As32[(r + 8) * PADW + kw];
                af[mi][2] = As32[r * PADW + kw + 4];
                af[mi][3] = As32[(r + 8) * PADW + kw + 4];
            }
#pragma unroll
            for (int nj = 0; nj < 8; ++nj) {
                const int n = wn + nj * 8 + grp;
                bfr[nj][0] = Bs32[n * PADW + kw];
                bfr[nj][1] = Bs32[n * PADW + kw + 4];
            }
#pragma unroll
            for (int mi = 0; mi < 2; ++mi)
#pragma unroll
                for (int nj = 0; nj < 8; ++nj)
                    mma_bf16(acc[mi][nj], af[mi], bfr[nj]);
        }
        __syncthreads();
    }

    // epilogue
#pragma unroll
    for (int mi = 0; mi < 2; ++mi) {
        const int rA = rowBase + wm + mi * 16 + grp;
#pragma unroll
        for (int nj = 0; nj < 8; ++nj) {
            const int col = colBase + wn + nj * 8 + tig * 2;
            const float bb0 = bias[col], bb1 = bias[col + 1];
            float v0 = acc[mi][nj][0] + bb0;
            float v1 = acc[mi][nj][1] + bb1;
            float v2 = acc[mi][nj][2] + bb0;
            float v3 = acc[mi][nj][3] + bb1;
            if (RELU) {
                v0 = fmaxf(v0, 0.f); v1 = fmaxf(v1, 0.f);
                v2 = fmaxf(v2, 0.f); v3 = fmaxf(v3, 0.f);
            }
            if (rA < M) {
                *(float2*)&Cf[(size_t)rA * DD + col] = make_float2(v0, v1);
                if (SPLIT) {
                    __nv_bfloat16 h0 = __float2bfloat16(v0), h1 = __float2bfloat16(v1);
                    __nv_bfloat162 hp; hp.x = h0; hp.y = h1;
                    __nv_bfloat162 lp;
                    lp.x = __float2bfloat16(v0 - __bfloat162float(h0));
                    lp.y = __float2bfloat16(v1 - __bfloat162float(h1));
                    *(__nv_bfloat162*)&Ch[(size_t)rA * DD + col] = hp;
                    *(__nv_bfloat162*)&Cl[(size_t)rA * DD + col] = lp;
                }
            }
            if (rA + 8 < M) {
                *(float2*)&Cf[(size_t)(rA + 8) * DD + col] = make_float2(v2, v3);
                if (SPLIT) {
                    __nv_bfloat16 h2 = __float2bfloat16(v2), h3 = __float2bfloat16(v3);
                    __nv_bfloat162 hp; hp.x = h2; hp.y = h3;
                    __nv_bfloat162 lp;
                    lp.x = __float2bfloat16(v2 - __bfloat162float(h2));
                    lp.y = __float2bfloat16(v3 - __bfloat162float(h3));
                    *(__nv_bfloat162*)&Ch[(size_t)(rA + 8) * DD + col] = hp;
                    *(__nv_bfloat162*)&Cl[(size_t)(rA + 8) * DD + col] = lp;
                }
            }
        }
    }
}

// ---------------- launch -----------------------------------------------------
extern "C" void kernel_launch(void* const* d_in, const int* in_sizes, int n_in,
                              void* d_out, int out_size) {
    const float* x     = (const float*)d_in[0];
    const int*   eidxW = (const int*)d_in[1];   // [2, E], int32 or int64 (auto-detected)
    const float* Wl1   = (const float*)d_in[2];
    const float* Wr1   = (const float*)d_in[3];
    const float* b1    = (const float*)d_in[4];
    const float* Wlin1 = (const float*)d_in[5];
    const float* blin1 = (const float*)d_in[6];
    const float* Wl2   = (const float*)d_in[7];
    const float* Wr2   = (const float*)d_in[8];
    const float* b2    = (const float*)d_in[9];
    const float* Wlin2 = (const float*)d_in[10];
    const float* blin2 = (const float*)d_in[11];
    float* out = (float*)d_out;

    float* h;   cudaGetSymbolAddress((void**)&h,   g_h);
    float* b1c; cudaGetSymbolAddress((void**)&b1c, g_b1);
    float* b2c; cudaGetSymbolAddress((void**)&b2c, g_b2);
    __nv_bfloat16 *xh, *xl, *aggh, *aggl, *hh, *hl;
    cudaGetSymbolAddress((void**)&xh, g_xh);
    cudaGetSymbolAddress((void**)&xl, g_xl);
    cudaGetSymbolAddress((void**)&aggh, g_aggh);
    cudaGetSymbolAddress((void**)&aggl, g_aggl);
    cudaGetSymbolAddress((void**)&hh, g_hh);
    cudaGetSymbolAddress((void**)&hl, g_hl);
    __nv_bfloat16 *B1h, *B1l, *B2h, *B2l, *B3h, *B3l, *B4h, *B4l;
    cudaGetSymbolAddress((void**)&B1h, g_B1h);
    cudaGetSymbolAddress((void**)&B1l, g_B1l);
    cudaGetSymbolAddress((void**)&B2h, g_B2h);
    cudaGetSymbolAddress((void**)&B2l, g_B2l);
    cudaGetSymbolAddress((void**)&B3h, g_B3h);
    cudaGetSymbolAddress((void**)&B3l, g_B3l);
    cudaGetSymbolAddress((void**)&B4h, g_B4h);
    cudaGetSymbolAddress((void**)&B4l, g_B4l);

    // 0) decode edge index (dtype-agnostic)
    detect_dtype<<<1, 1024>>>(eidxW);
    extract_edges<<<(EE + 255) / 256, 256>>>(eidxW);

    // 1) weight prep: combine parallel linear into root, transpose+split to bf16
    prep_weights<<<(DD * DD + 255) / 256, 256>>>(Wr1, Wlin1, b1, blin1, Wr2, Wlin2, b2, blin2);
    transpose_split<<<dim3(DD, 4), DD>>>(Wl1, Wl2);
    split_x<<<(int)(((size_t)NN * DD + 255) / 256), 256>>>(x);

    // 2) build CSR (by dst) once
    zero_counts<<<(NN + 255) / 256, 256>>>();
    hist_kernel<<<(EE + 255) / 256, 256>>>();
    scanA<<<NBLK, SCAN_B>>>();
    scanB<<<1, 32>>>();
    scanC<<<(NN + 255) / 256, 256>>>();
    fill_csr<<<(EE + 255) / 256, 256>>>();

    dim3 gemmGrid((NN + G_BM - 1) / G_BM, DD / G_BN);

    // 3) layer 1
    aggregate_split<<<NN, 256>>>(x, aggh, aggl);
    gemm_mma<1, 1><<<gemmGrid, 256>>>(aggh, aggl, xh, xl,
                                      B1h, B1l, B2h, B2l,
                                      b1c, h, hh, hl, NN);

    // 4) layer 2
    aggregate_split<<<NN, 256>>>(h, aggh, aggl);
    gemm_mma<0, 0><<<gemmGrid, 256>>>(aggh, aggl, hh, hl,
                                      B3h, B3l, B4h, B4l,
                                      b2c, out, nullptr, nullptr, NN);
}

// round 8
// speedup vs baseline: 2.0480x; 1.2729x over previous
#include <cuda_runtime.h>
#include <cuda_bf16.h>
#include <cstdint>

#define NN 100000
#define EE 1600000
#define DD 256
#define SCAN_B 1024
#define NBLK ((NN + SCAN_B - 1) / SCAN_B)   // 98

// ---------------- scratch (device globals; no allocations allowed) ----------
__device__ __nv_bfloat16 g_xh[(size_t)NN * DD];
__device__ __nv_bfloat16 g_xl[(size_t)NN * DD];
__device__ __nv_bfloat16 g_aggh[(size_t)NN * DD];
__device__ __nv_bfloat16 g_aggl[(size_t)NN * DD];
__device__ __nv_bfloat16 g_hh[(size_t)NN * DD];
__device__ __nv_bfloat16 g_hl[(size_t)NN * DD];
__device__ float g_h[(size_t)NN * DD];       // layer-1 hidden fp32 (for aggregation 2)
__device__ int   g_src[EE];
__device__ int   g_dst[EE];
__device__ int   g_is64;
__device__ int   g_deg[NN];
__device__ int   g_scan[NN];
__device__ int   g_rowptr[NN + 1];
__device__ int   g_cursor[NN];
__device__ int   g_csr_src[EE];
__device__ int   g_bsum[NBLK];
__device__ int   g_boff[NBLK];
__device__ float g_W1[DD * DD];              // Wr1 + Wlin1 (fp32 combined)
__device__ float g_W2[DD * DD];              // Wr2 + Wlin2
__device__ float g_b1[DD];
__device__ float g_b2[DD];
// transposed + split B matrices: layout [n][k] (n-major), bf16
__device__ __nv_bfloat16 g_B1h[DD * DD], g_B1l[DD * DD];   // Wl1
__device__ __nv_bfloat16 g_B2h[DD * DD], g_B2l[DD * DD];   // Wr1+Wlin1
__device__ __nv_bfloat16 g_B3h[DD * DD], g_B3l[DD * DD];   // Wl2
__device__ __nv_bfloat16 g_B4h[DD * DD], g_B4l[DD * DD];   // Wr2+Wlin2

// ---------------- PTX helpers ------------------------------------------------
__device__ __forceinline__ void mma_bf16(float* d, const uint32_t* a, const uint32_t* b) {
    asm volatile(
        "mma.sync.aligned.m16n8k16.row.col.f32.bf16.bf16.f32 "
        "{%0,%1,%2,%3}, {%4,%5,%6,%7}, {%8,%9}, {%0,%1,%2,%3};\n"
        : "+f"(d[0]), "+f"(d[1]), "+f"(d[2]), "+f"(d[3])
        : "r"(a[0]), "r"(a[1]), "r"(a[2]), "r"(a[3]), "r"(b[0]), "r"(b[1]));
}

__device__ __forceinline__ void cp_async16(uint32_t saddr, const void* gaddr) {
    asm volatile("cp.async.cg.shared.global [%0], [%1], 16;\n" :: "r"(saddr), "l"(gaddr));
}

__device__ __forceinline__ uint32_t smem_u32(const void* p) {
    return (uint32_t)__cvta_generic_to_shared(p);
}

// ---------------- edge dtype detection + extraction -------------------------
__global__ void detect_dtype(const int* __restrict__ w) {
    __shared__ int nz;
    if (threadIdx.x == 0) nz = 0;
    __syncthreads();
    int v = w[2 * threadIdx.x + 1];
    if (v != 0) atomicOr(&nz, 1);
    __syncthreads();
    if (threadIdx.x == 0) g_is64 = (nz == 0) ? 1 : 0;
}

// also zeroes deg/cursor (fused; no dependency within this kernel)
__global__ void extract_edges(const int* __restrict__ w) {
    int e = blockIdx.x * blockDim.x + threadIdx.x;
    if (e < NN) { g_deg[e] = 0; g_cursor[e] = 0; }
    if (e >= EE) return;
    int s, d;
    if (g_is64) {
        s = w[2 * (size_t)e];
        d = w[2 * ((size_t)EE + e)];
    } else {
        s = w[e];
        d = w[EE + e];
    }
    s = min(max(s, 0), NN - 1);
    d = min(max(d, 0), NN - 1);
    g_src[e] = s;
    g_dst[e] = d;
}

// ---------------- prep: combine weights, split+transpose --------------------
__global__ void prep_weights(const float* __restrict__ Wr1, const float* __restrict__ Wlin1,
                             const float* __restrict__ b1,  const float* __restrict__ blin1,
                             const float* __restrict__ Wr2, const float* __restrict__ Wlin2,
                             const float* __restrict__ b2,  const float* __restrict__ blin2) {
    int i = blockIdx.x * blockDim.x + threadIdx.x;
    if (i < DD * DD) {
        g_W1[i] = Wr1[i] + Wlin1[i];
        g_W2[i] = Wr2[i] + Wlin2[i];
    }
    if (i < DD) {
        g_b1[i] = b1[i] + blin1[i];
        g_b2[i] = b2[i] + blin2[i];
    }
}

// transpose [k][n] -> [n][k], split into hi/lo bf16
__global__ void transpose_split(const float* __restrict__ Wl1, const float* __restrict__ Wl2) {
    int k = blockIdx.x, n = threadIdx.x;
    const float* src;
    __nv_bfloat16 *dh, *dl;
    switch (blockIdx.y) {
        case 0:  src = Wl1;  dh = g_B1h; dl = g_B1l; break;
        case 1:  src = g_W1; dh = g_B2h; dl = g_B2l; break;
        case 2:  src = Wl2;  dh = g_B3h; dl = g_B3l; break;
        default: src = g_W2; dh = g_B4h; dl = g_B4l; break;
    }
    float v = src[k * DD + n];
    __nv_bfloat16 hi = __float2bfloat16(v);
    float lo = v - __bfloat162float(hi);
    dh[n * DD + k] = hi;
    dl[n * DD + k] = __float2bfloat16(lo);
}

__global__ void split_x(const float* __restrict__ x) {
    size_t i = (size_t)blockIdx.x * blockDim.x + threadIdx.x;
    if (i >= (size_t)NN * DD) return;
    float v = x[i];
    __nv_bfloat16 hi = __float2bfloat16(v);
    float lo = v - __bfloat162float(hi);
    g_xh[i] = hi;
    g_xl[i] = __float2bfloat16(lo);
}

// ---------------- CSR build --------------------------------------------------
__global__ void hist_kernel() {
    int e = blockIdx.x * blockDim.x + threadIdx.x;
    if (e < EE) atomicAdd(&g_deg[g_dst[e]], 1);
}

__global__ void scanA() {
    __shared__ int sh[SCAN_B];
    int i = blockIdx.x * SCAN_B + threadIdx.x;
    sh[threadIdx.x] = (i < NN) ? g_deg[i] : 0;
    __syncthreads();
    for (int off = 1; off < SCAN_B; off <<= 1) {
        int t = (threadIdx.x >= off) ? sh[threadIdx.x - off] : 0;
        __syncthreads();
        sh[threadIdx.x] += t;
        __syncthreads();
    }
    if (i < NN) g_scan[i] = sh[threadIdx.x];
    if (threadIdx.x == SCAN_B - 1) g_bsum[blockIdx.x] = sh[SCAN_B - 1];
}

__global__ void scanB() {
    if (threadIdx.x == 0 && blockIdx.x == 0) {
        int run = 0;
        for (int b = 0; b < NBLK; b++) { int t = g_bsum[b]; g_boff[b] = run; run += t; }
    }
}

__global__ void scanC() {
    int i = blockIdx.x * blockDim.x + threadIdx.x;
    if (i < NN) g_rowptr[i] = g_scan[i] - g_deg[i] + g_boff[i / SCAN_B];
    if (i == 0) g_rowptr[NN] = EE;
}

__global__ void fill_csr() {
    int e = blockIdx.x * blockDim.x + threadIdx.x;
    if (e < EE) {
        int d = g_dst[e];
        int pos = g_rowptr[d] + atomicAdd(&g_cursor[d], 1);
        g_csr_src[pos] = g_src[e];
    }
}

// ---------------- mean aggregation: one WARP per dst node, float4, MLP=8 ----
__global__ void __launch_bounds__(256) aggregate_split(
    const float* __restrict__ feat,
    __nv_bfloat16* __restrict__ oh,
    __nv_bfloat16* __restrict__ ol) {
    int node = blockIdx.x * 8 + (threadIdx.x >> 5);
    int lane = threadIdx.x & 31;
    if (node >= NN) return;
    int start = g_rowptr[node];
    int end   = g_rowptr[node + 1];
    const float4* f4 = (const float4*)feat;      // 64 float4 per row

    float4 a0 = make_float4(0.f, 0.f, 0.f, 0.f);
    float4 a1 = make_float4(0.f, 0.f, 0.f, 0.f);

    for (int base = start; base < end; base += 32) {
        int cnt = min(32, end - base);
        int my = (base + lane < end) ? g_csr_src[base + lane] : 0;
        int t = 0;
        for (; t + 4 <= cnt; t += 4) {
            int i0 = __shfl_sync(0xffffffffu, my, t);
            int i1 = __shfl_sync(0xffffffffu, my, t + 1);
            int i2 = __shfl_sync(0xffffffffu, my, t + 2);
            int i3 = __shfl_sync(0xffffffffu, my, t + 3);
            const float4* p0 = f4 + (size_t)i0 * 64;
            const float4* p1 = f4 + (size_t)i1 * 64;
            const float4* p2 = f4 + (size_t)i2 * 64;
            const float4* p3 = f4 + (size_t)i3 * 64;
            float4 v00 = p0[lane], v01 = p0[lane + 32];
            float4 v10 = p1[lane], v11 = p1[lane + 32];
            float4 v20 = p2[lane], v21 = p2[lane + 32];
            float4 v30 = p3[lane], v31 = p3[lane + 32];
            a0.x += v00.x + v10.x + v20.x + v30.x;
            a0.y += v00.y + v10.y + v20.y + v30.y;
            a0.z += v00.z + v10.z + v20.z + v30.z;
            a0.w += v00.w + v10.w + v20.w + v30.w;
            a1.x += v01.x + v11.x + v21.x + v31.x;
            a1.y += v01.y + v11.y + v21.y + v31.y;
            a1.z += v01.z + v11.z + v21.z + v31.z;
            a1.w += v01.w + v11.w + v21.w + v31.w;
        }
        for (; t < cnt; ++t) {
            int i0 = __shfl_sync(0xffffffffu, my, t);
            const float4* p0 = f4 + (size_t)i0 * 64;
            float4 v00 = p0[lane], v01 = p0[lane + 32];
            a0.x += v00.x; a0.y += v00.y; a0.z += v00.z; a0.w += v00.w;
            a1.x += v01.x; a1.y += v01.y; a1.z += v01.z; a1.w += v01.w;
        }
    }

    float scale = (end > start) ? (1.f / (float)(end - start)) : 0.f;
    float o[8] = {a0.x * scale, a0.y * scale, a0.z * scale, a0.w * scale,
                  a1.x * scale, a1.y * scale, a1.z * scale, a1.w * scale};
    size_t rowOff = (size_t)node * DD;
#pragma unroll
    for (int half = 0; half < 2; ++half) {
        int col = half * 128 + lane * 4;
        __nv_bfloat16 h0 = __float2bfloat16(o[half * 4 + 0]);
        __nv_bfloat16 h1 = __float2bfloat16(o[half * 4 + 1]);
        __nv_bfloat16 h2 = __float2bfloat16(o[half * 4 + 2]);
        __nv_bfloat16 h3 = __float2bfloat16(o[half * 4 + 3]);
        __nv_bfloat162 hp0; hp0.x = h0; hp0.y = h1;
        __nv_bfloat162 hp1; hp1.x = h2; hp1.y = h3;
        __nv_bfloat162 lp0, lp1;
        lp0.x = __float2bfloat16(o[half * 4 + 0] - __bfloat162float(h0));
        lp0.y = __float2bfloat16(o[half * 4 + 1] - __bfloat162float(h1));
        lp1.x = __float2bfloat16(o[half * 4 + 2] - __bfloat162float(h2));
        lp1.y = __float2bfloat16(o[half * 4 + 3] - __bfloat162float(h3));
        *(__nv_bfloat162*)&oh[rowOff + col]     = hp0;
        *(__nv_bfloat162*)&oh[rowOff + col + 2] = hp1;
        *(__nv_bfloat162*)&ol[rowOff + col]     = lp0;
        *(__nv_bfloat162*)&ol[rowOff + col + 2] = lp1;
    }
}

// ---------------- split-bf16 double GEMM via tensor cores -------------------
// C = A1@B1 + A2@B2 + bias, each product as Ahi@Bhi + Ahi@Blo + Alo@Bhi
// A*: [M x 256] row-major bf16.  B*: [256 n][256 k] n-major (pre-transposed) bf16.
// Block tile 128x128, 8 warps (warp tile 32x64), BK=64, double-buffered cp.async.
// Dynamic smem, rows padded to 36 words: fragment LDS banks (4r+kw)%32 all
// distinct; cp.async STS conflict-free per 8-lane phase.
#define G_BM 128
#define G_BN 128
#define G_BK 64
#define PADW 36                 // words per smem row (32 data + 4 pad)
#define NSTAGES 24              // 6 segments * (256/64)
#define A_BUF_ELEMS (G_BM * PADW * 2)           // bf16 elems per buffer
#define GEMM_SMEM_BYTES (4 * G_BM * PADW * 2 * 2)  // As[2]+Bs[2] = 73728

template <int RELU, int SPLIT>
__global__ void __launch_bounds__(256, 2) gemm_mma(
    const __nv_bfloat16* __restrict__ A1h, const __nv_bfloat16* __restrict__ A1l,
    const __nv_bfloat16* __restrict__ A2h, const __nv_bfloat16* __restrict__ A2l,
    const __nv_bfloat16* __restrict__ B1h, const __nv_bfloat16* __restrict__ B1l,
    const __nv_bfloat16* __restrict__ B2h, const __nv_bfloat16* __restrict__ B2l,
    const float* __restrict__ bias,
    float* __restrict__ Cf, __nv_bfloat16* __restrict__ Ch, __nv_bfloat16* __restrict__ Cl,
    int M)
{
    extern __shared__ __nv_bfloat16 dsm[];
    __nv_bfloat16* AsB = dsm;                       // [2][128][72]
    __nv_bfloat16* BsB = dsm + 2 * A_BUF_ELEMS;     // [2][128][72]

    const int tid  = threadIdx.x;
    const int wid  = tid >> 5;
    const int lane = tid & 31;
    const int grp  = lane >> 2;      // 0..7
    const int tig  = lane & 3;       // 0..3
    const int wm   = (wid & 3) * 32; // warp M offset (4 warps)
    const int wn   = (wid >> 2) * 64;// warp N offset (2 warps)
    const int rowBase = blockIdx.x * G_BM;
    const int colBase = blockIdx.y * G_BN;

    const __nv_bfloat16* Aseg[6] = {A1h, A1h, A1l, A2h, A2h, A2l};
    const __nv_bfloat16* Bseg[6] = {B1h, B1l, B1h, B2h, B2l, B2h};

    float acc[2][8][4];
#pragma unroll
    for (int mi = 0; mi < 2; mi++)
#pragma unroll
        for (int nj = 0; nj < 8; nj++)
#pragma unroll
            for (int c = 0; c < 4; c++) acc[mi][nj][c] = 0.f;

    auto load_stage = [&](int stage, int buf) {
        const int s  = stage >> 2;
        const int kk = (stage & 3) * G_BK;
        const __nv_bfloat16* A = Aseg[s];
        const __nv_bfloat16* B = Bseg[s];
        // A/B tiles: 128 rows x 128B = 1024 chunks of 16B each; 4 per thread
#pragma unroll
        for (int i = 0; i < 4; i++) {
            int id  = tid + i * 256;
            int row = id >> 3;        // 0..127
            int c16 = id & 7;         // 16B chunk within row
            int grow = min(rowBase + row, M - 1);
            uint32_t soff = (uint32_t)((buf * G_BM + row) * (PADW * 2) + c16 * 8) * 2;
            cp_async16(smem_u32(AsB) + soff, A + (size_t)grow * DD + kk + c16 * 8);
            uint32_t soffB = (uint32_t)((buf * G_BM + row) * (PADW * 2) + c16 * 8) * 2;
            cp_async16(smem_u32(BsB) + soffB, B + (size_t)(colBase + row) * DD + kk + c16 * 8);
        }
    };

    load_stage(0, 0);
    asm volatile("cp.async.commit_group;\n");

    for (int stage = 0; stage < NSTAGES; ++stage) {
        const int buf = stage & 1;
        if (stage + 1 < NSTAGES) {
            load_stage(stage + 1, buf ^ 1);
            asm volatile("cp.async.commit_group;\n");
            asm volatile("cp.async.wait_group 1;\n");
        } else {
            asm volatile("cp.async.wait_group 0;\n");
        }
        __syncthreads();

        const uint32_t* As32 = (const uint32_t*)AsB + buf * G_BM * PADW;
        const uint32_t* Bs32 = (const uint32_t*)BsB + buf * G_BM * PADW;

#pragma unroll
        for (int ks = 0; ks < 4; ++ks) {
            const int kw = ks * 8 + tig;   // word column (k/2)
            uint32_t af[2][4], bfr[8][2];
#pragma unroll
            for (int mi = 0; mi < 2; ++mi) {
                const int r = wm + mi * 16 + grp;
                af[mi][0] = As32[r * PADW + kw];
                af[mi][1] = As32[(r + 8) * PADW + kw];
                af[mi][2] = As32[r * PADW + kw + 4];
                af[mi][3] = As32[(r + 8) * PADW + kw + 4];
            }
#pragma unroll
            for (int nj = 0; nj < 8; ++nj) {
                const int n = wn + nj * 8 + grp;
                bfr[nj][0] = Bs32[n * PADW + kw];
                bfr[nj][1] = Bs32[n * PADW + kw + 4];
            }
#pragma unroll
            for (int mi = 0; mi < 2; ++mi)
#pragma unroll
                for (int nj = 0; nj < 8; ++nj)
                    mma_bf16(acc[mi][nj], af[mi], bfr[nj]);
        }
        __syncthreads();
    }

    // epilogue
#pragma unroll
    for (int mi = 0; mi < 2; ++mi) {
        const int rA = rowBase + wm + mi * 16 + grp;
#pragma unroll
        for (int nj = 0; nj < 8; ++nj) {
            const int col = colBase + wn + nj * 8 + tig * 2;
            const float bb0 = bias[col], bb1 = bias[col + 1];
            float v0 = acc[mi][nj][0] + bb0;
            float v1 = acc[mi][nj][1] + bb1;
            float v2 = acc[mi][nj][2] + bb0;
            float v3 = acc[mi][nj][3] + bb1;
            if (RELU) {
                v0 = fmaxf(v0, 0.f); v1 = fmaxf(v1, 0.f);
                v2 = fmaxf(v2, 0.f); v3 = fmaxf(v3, 0.f);
            }
            if (rA < M) {
                *(float2*)&Cf[(size_t)rA * DD + col] = make_float2(v0, v1);
                if (SPLIT) {
                    __nv_bfloat16 h0 = __float2bfloat16(v0), h1 = __float2bfloat16(v1);
                    __nv_bfloat162 hp; hp.x = h0; hp.y = h1;
                    __nv_bfloat162 lp;
                    lp.x = __float2bfloat16(v0 - __bfloat162float(h0));
                    lp.y = __float2bfloat16(v1 - __bfloat162float(h1));
                    *(__nv_bfloat162*)&Ch[(size_t)rA * DD + col] = hp;
                    *(__nv_bfloat162*)&Cl[(size_t)rA * DD + col] = lp;
                }
            }
            if (rA + 8 < M) {
                *(float2*)&Cf[(size_t)(rA + 8) * DD + col] = make_float2(v2, v3);
                if (SPLIT) {
                    __nv_bfloat16 h2 = __float2bfloat16(v2), h3 = __float2bfloat16(v3);
                    __nv_bfloat162 hp; hp.x = h2; hp.y = h3;
                    __nv_bfloat162 lp;
                    lp.x = __float2bfloat16(v2 - __bfloat162float(h2));
                    lp.y = __float2bfloat16(v3 - __bfloat162float(h3));
                    *(__nv_bfloat162*)&Ch[(size_t)(rA + 8) * DD + col] = hp;
                    *(__nv_bfloat162*)&Cl[(size_t)(rA + 8) * DD + col] = lp;
                }
            }
        }
    }
}

// ---------------- launch -----------------------------------------------------
extern "C" void kernel_launch(void* const* d_in, const int* in_sizes, int n_in,
                              void* d_out, int out_size) {
    const float* x     = (const float*)d_in[0];
    const int*   eidxW = (const int*)d_in[1];   // [2, E], int32 or int64 (auto-detected)
    const float* Wl1   = (const float*)d_in[2];
    const float* Wr1   = (const float*)d_in[3];
    const float* b1    = (const float*)d_in[4];
    const float* Wlin1 = (const float*)d_in[5];
    const float* blin1 = (const float*)d_in[6];
    const float* Wl2   = (const float*)d_in[7];
    const float* Wr2   = (const float*)d_in[8];
    const float* b2    = (const float*)d_in[9];
    const float* Wlin2 = (const float*)d_in[10];
    const float* blin2 = (const float*)d_in[11];
    float* out = (float*)d_out;

    float* h;   cudaGetSymbolAddress((void**)&h,   g_h);
    float* b1c; cudaGetSymbolAddress((void**)&b1c, g_b1);
    float* b2c; cudaGetSymbolAddress((void**)&b2c, g_b2);
    __nv_bfloat16 *xh, *xl, *aggh, *aggl, *hh, *hl;
    cudaGetSymbolAddress((void**)&xh, g_xh);
    cudaGetSymbolAddress((void**)&xl, g_xl);
    cudaGetSymbolAddress((void**)&aggh, g_aggh);
    cudaGetSymbolAddress((void**)&aggl, g_aggl);
    cudaGetSymbolAddress((void**)&hh, g_hh);
    cudaGetSymbolAddress((void**)&hl, g_hl);
    __nv_bfloat16 *B1h, *B1l, *B2h, *B2l, *B3h, *B3l, *B4h, *B4l;
    cudaGetSymbolAddress((void**)&B1h, g_B1h);
    cudaGetSymbolAddress((void**)&B1l, g_B1l);
    cudaGetSymbolAddress((void**)&B2h, g_B2h);
    cudaGetSymbolAddress((void**)&B2l, g_B2l);
    cudaGetSymbolAddress((void**)&B3h, g_B3h);
    cudaGetSymbolAddress((void**)&B3l, g_B3l);
    cudaGetSymbolAddress((void**)&B4h, g_B4h);
    cudaGetSymbolAddress((void**)&B4l, g_B4l);

    cudaFuncSetAttribute(gemm_mma<1, 1>, cudaFuncAttributeMaxDynamicSharedMemorySize,
                         GEMM_SMEM_BYTES);
    cudaFuncSetAttribute(gemm_mma<0, 0>, cudaFuncAttributeMaxDynamicSharedMemorySize,
                         GEMM_SMEM_BYTES);

    // 0) decode edge index (dtype-agnostic); extract also zeroes deg/cursor
    detect_dtype<<<1, 1024>>>(eidxW);
    extract_edges<<<(EE + 255) / 256, 256>>>(eidxW);

    // 1) weight prep (independent; placed here so hist is the profiled launch)
    prep_weights<<<(DD * DD + 255) / 256, 256>>>(Wr1, Wlin1, b1, blin1, Wr2, Wlin2, b2, blin2);

    // 2) build CSR (by dst) once
    hist_kernel<<<(EE + 255) / 256, 256>>>();
    scanA<<<NBLK, SCAN_B>>>();
    scanB<<<1, 32>>>();
    scanC<<<(NN + 255) / 256, 256>>>();
    fill_csr<<<(EE + 255) / 256, 256>>>();

    // 3) remaining prep
    transpose_split<<<dim3(DD, 4), DD>>>(Wl1, Wl2);
    split_x<<<(int)(((size_t)NN * DD + 255) / 256), 256>>>(x);

    dim3 gemmGrid((NN + G_BM - 1) / G_BM, DD / G_BN);
    const int aggBlocks = (NN + 7) / 8;

    // 4) layer 1
    aggregate_split<<<aggBlocks, 256>>>(x, aggh, aggl);
    gemm_mma<1, 1><<<gemmGrid, 256, GEMM_SMEM_BYTES>>>(aggh, aggl, xh, xl,
                                                       B1h, B1l, B2h, B2l,
                                                       b1c, h, hh, hl, NN);

    // 5) layer 2
    aggregate_split<<<aggBlocks, 256>>>(h, aggh, aggl);
    gemm_mma<0, 0><<<gemmGrid, 256, GEMM_SMEM_BYTES>>>(aggh, aggl, hh, hl,
                                                       B3h, B3l, B4h, B4l,
                                                       b2c, out, nullptr, nullptr, NN);
}

// round 10
// speedup vs baseline: 2.1842x; 1.0665x over previous
#include <cuda_runtime.h>
#include <cuda_bf16.h>
#include <cstdint>

#define NN 100000
#define EE 1600000
#define DD 256
#define SCAN_B 1024
#define NBLK ((NN + SCAN_B - 1) / SCAN_B)   // 98

// ---------------- scratch (device globals; no allocations allowed) ----------
__device__ __nv_bfloat16 g_xh[(size_t)NN * DD];
__device__ __nv_bfloat16 g_xl[(size_t)NN * DD];
__device__ __nv_bfloat16 g_aggh[(size_t)NN * DD];
__device__ __nv_bfloat16 g_aggl[(size_t)NN * DD];
__device__ __nv_bfloat16 g_hh[(size_t)NN * DD];
__device__ __nv_bfloat16 g_hl[(size_t)NN * DD];
__device__ int   g_src[EE];
__device__ int   g_dst[EE];
__device__ int   g_is64;
__device__ int   g_deg[NN];
__device__ int   g_scan[NN];
__device__ int   g_rowptr[NN + 1];
__device__ int   g_cursor[NN];
__device__ int   g_csr_src[EE];
__device__ int   g_bsum[NBLK];
__device__ int   g_boff[NBLK];
__device__ float g_W1[DD * DD];              // Wr1 + Wlin1 (fp32 combined)
__device__ float g_W2[DD * DD];              // Wr2 + Wlin2
__device__ float g_b1[DD];
__device__ float g_b2[DD];
// transposed + split B matrices: layout [n][k] (n-major), bf16
__device__ __nv_bfloat16 g_B1h[DD * DD], g_B1l[DD * DD];   // Wl1
__device__ __nv_bfloat16 g_B2h[DD * DD], g_B2l[DD * DD];   // Wr1+Wlin1
__device__ __nv_bfloat16 g_B3h[DD * DD], g_B3l[DD * DD];   // Wl2
__device__ __nv_bfloat16 g_B4h[DD * DD], g_B4l[DD * DD];   // Wr2+Wlin2

// ---------------- PTX helpers ------------------------------------------------
__device__ __forceinline__ void mma_bf16(float* d, const uint32_t* a, const uint32_t* b) {
    asm volatile(
        "mma.sync.aligned.m16n8k16.row.col.f32.bf16.bf16.f32 "
        "{%0,%1,%2,%3}, {%4,%5,%6,%7}, {%8,%9}, {%0,%1,%2,%3};\n"
        : "+f"(d[0]), "+f"(d[1]), "+f"(d[2]), "+f"(d[3])
        : "r"(a[0]), "r"(a[1]), "r"(a[2]), "r"(a[3]), "r"(b[0]), "r"(b[1]));
}

__device__ __forceinline__ void cp_async16(uint32_t saddr, const void* gaddr) {
    asm volatile("cp.async.cg.shared.global [%0], [%1], 16;\n" :: "r"(saddr), "l"(gaddr));
}

__device__ __forceinline__ uint32_t smem_u32(const void* p) {
    return (uint32_t)__cvta_generic_to_shared(p);
}

// ---------------- edge dtype detection + extraction -------------------------
__global__ void detect_dtype(const int* __restrict__ w) {
    __shared__ int nz;
    if (threadIdx.x == 0) nz = 0;
    __syncthreads();
    int v = w[2 * threadIdx.x + 1];
    if (v != 0) atomicOr(&nz, 1);
    __syncthreads();
    if (threadIdx.x == 0) g_is64 = (nz == 0) ? 1 : 0;
}

// also zeroes deg/cursor (fused; no dependency within this kernel)
__global__ void extract_edges(const int* __restrict__ w) {
    int e = blockIdx.x * blockDim.x + threadIdx.x;
    if (e < NN) { g_deg[e] = 0; g_cursor[e] = 0; }
    if (e >= EE) return;
    int s, d;
    if (g_is64) {
        s = w[2 * (size_t)e];
        d = w[2 * ((size_t)EE + e)];
    } else {
        s = w[e];
        d = w[EE + e];
    }
    s = min(max(s, 0), NN - 1);
    d = min(max(d, 0), NN - 1);
    g_src[e] = s;
    g_dst[e] = d;
}

// ---------------- prep: combine weights, split+transpose --------------------
__global__ void prep_weights(const float* __restrict__ Wr1, const float* __restrict__ Wlin1,
                             const float* __restrict__ b1,  const float* __restrict__ blin1,
                             const float* __restrict__ Wr2, const float* __restrict__ Wlin2,
                             const float* __restrict__ b2,  const float* __restrict__ blin2) {
    int i = blockIdx.x * blockDim.x + threadIdx.x;
    if (i < DD * DD) {
        g_W1[i] = Wr1[i] + Wlin1[i];
        g_W2[i] = Wr2[i] + Wlin2[i];
    }
    if (i < DD) {
        g_b1[i] = b1[i] + blin1[i];
        g_b2[i] = b2[i] + blin2[i];
    }
}

// transpose [k][n] -> [n][k], split into hi/lo bf16
__global__ void transpose_split(const float* __restrict__ Wl1, const float* __restrict__ Wl2) {
    int k = blockIdx.x, n = threadIdx.x;
    const float* src;
    __nv_bfloat16 *dh, *dl;
    switch (blockIdx.y) {
        case 0:  src = Wl1;  dh = g_B1h; dl = g_B1l; break;
        case 1:  src = g_W1; dh = g_B2h; dl = g_B2l; break;
        case 2:  src = Wl2;  dh = g_B3h; dl = g_B3l; break;
        default: src = g_W2; dh = g_B4h; dl = g_B4l; break;
    }
    float v = src[k * DD + n];
    __nv_bfloat16 hi = __float2bfloat16(v);
    float lo = v - __bfloat162float(hi);
    dh[n * DD + k] = hi;
    dl[n * DD + k] = __float2bfloat16(lo);
}

__global__ void split_x(const float* __restrict__ x) {
    size_t i = (size_t)blockIdx.x * blockDim.x + threadIdx.x;
    if (i >= (size_t)NN * DD) return;
    float v = x[i];
    __nv_bfloat16 hi = __float2bfloat16(v);
    float lo = v - __bfloat162float(hi);
    g_xh[i] = hi;
    g_xl[i] = __float2bfloat16(lo);
}

// ---------------- CSR build --------------------------------------------------
__global__ void hist_kernel() {
    int e = blockIdx.x * blockDim.x + threadIdx.x;
    if (e < EE) atomicAdd(&g_deg[g_dst[e]], 1);
}

__global__ void scanA() {
    __shared__ int sh[SCAN_B];
    int i = blockIdx.x * SCAN_B + threadIdx.x;
    sh[threadIdx.x] = (i < NN) ? g_deg[i] : 0;
    __syncthreads();
    for (int off = 1; off < SCAN_B; off <<= 1) {
        int t = (threadIdx.x >= off) ? sh[threadIdx.x - off] : 0;
        __syncthreads();
        sh[threadIdx.x] += t;
        __syncthreads();
    }
    if (i < NN) g_scan[i] = sh[threadIdx.x];
    if (threadIdx.x == SCAN_B - 1) g_bsum[blockIdx.x] = sh[SCAN_B - 1];
}

__global__ void scanB() {
    if (threadIdx.x == 0 && blockIdx.x == 0) {
        int run = 0;
        for (int b = 0; b < NBLK; b++) { int t = g_bsum[b]; g_boff[b] = run; run += t; }
    }
}

__global__ void scanC() {
    int i = blockIdx.x * blockDim.x + threadIdx.x;
    if (i < NN) g_rowptr[i] = g_scan[i] - g_deg[i] + g_boff[i / SCAN_B];
    if (i == 0) g_rowptr[NN] = EE;
}

__global__ void fill_csr() {
    int e = blockIdx.x * blockDim.x + threadIdx.x;
    if (e < EE) {
        int d = g_dst[e];
        int pos = g_rowptr[d] + atomicAdd(&g_cursor[d], 1);
        g_csr_src[pos] = g_src[e];
    }
}

// ---------------- mean aggregation: one WARP per dst node -------------------
// INBF=0: gather fp32 feat rows.  INBF=1: gather bf16 hi/lo rows, v = hi+lo.
template <int INBF>
__global__ void __launch_bounds__(256) aggregate_split(
    const float* __restrict__ feat,
    const __nv_bfloat16* __restrict__ fh, const __nv_bfloat16* __restrict__ fl,
    __nv_bfloat16* __restrict__ oh, __nv_bfloat16* __restrict__ ol) {
    int node = blockIdx.x * 8 + (threadIdx.x >> 5);
    int lane = threadIdx.x & 31;
    if (node >= NN) return;
    int start = g_rowptr[node];
    int end   = g_rowptr[node + 1];

    float acc[8] = {0.f, 0.f, 0.f, 0.f, 0.f, 0.f, 0.f, 0.f};

    if (INBF == 0) {
        const float4* f4 = (const float4*)feat;  // 64 float4 per row
        for (int base = start; base < end; base += 32) {
            int cnt = min(32, end - base);
            int my = (base + lane < end) ? g_csr_src[base + lane] : 0;
            int t = 0;
            for (; t + 4 <= cnt; t += 4) {
                int i0 = __shfl_sync(0xffffffffu, my, t);
                int i1 = __shfl_sync(0xffffffffu, my, t + 1);
                int i2 = __shfl_sync(0xffffffffu, my, t + 2);
                int i3 = __shfl_sync(0xffffffffu, my, t + 3);
                const float4* p0 = f4 + (size_t)i0 * 64;
                const float4* p1 = f4 + (size_t)i1 * 64;
                const float4* p2 = f4 + (size_t)i2 * 64;
                const float4* p3 = f4 + (size_t)i3 * 64;
                float4 v00 = p0[lane], v01 = p0[lane + 32];
                float4 v10 = p1[lane], v11 = p1[lane + 32];
                float4 v20 = p2[lane], v21 = p2[lane + 32];
                float4 v30 = p3[lane], v31 = p3[lane + 32];
                acc[0] += (v00.x + v10.x) + (v20.x + v30.x);
                acc[1] += (v00.y + v10.y) + (v20.y + v30.y);
                acc[2] += (v00.z + v10.z) + (v20.z + v30.z);
                acc[3] += (v00.w + v10.w) + (v20.w + v30.w);
                acc[4] += (v01.x + v11.x) + (v21.x + v31.x);
                acc[5] += (v01.y + v11.y) + (v21.y + v31.y);
                acc[6] += (v01.z + v11.z) + (v21.z + v31.z);
                acc[7] += (v01.w + v11.w) + (v21.w + v31.w);
            }
            for (; t < cnt; ++t) {
                int i0 = __shfl_sync(0xffffffffu, my, t);
                const float4* p0 = f4 + (size_t)i0 * 64;
                float4 v00 = p0[lane], v01 = p0[lane + 32];
                acc[0] += v00.x; acc[1] += v00.y; acc[2] += v00.z; acc[3] += v00.w;
                acc[4] += v01.x; acc[5] += v01.y; acc[6] += v01.z; acc[7] += v01.w;
            }
        }
    } else {
        const uint4* H = (const uint4*)fh;   // 32 uint4 (8 bf16 each) per row
        const uint4* L = (const uint4*)fl;
        for (int base = start; base < end; base += 32) {
            int cnt = min(32, end - base);
            int my = (base + lane < end) ? g_csr_src[base + lane] : 0;
            int t = 0;
            for (; t + 2 <= cnt; t += 2) {
                int i0 = __shfl_sync(0xffffffffu, my, t);
                int i1 = __shfl_sync(0xffffffffu, my, t + 1);
                uint4 h0 = H[(size_t)i0 * 32 + lane];
                uint4 l0 = L[(size_t)i0 * 32 + lane];
                uint4 h1 = H[(size_t)i1 * 32 + lane];
                uint4 l1 = L[(size_t)i1 * 32 + lane];
                const uint32_t* hw0 = (const uint32_t*)&h0;
                const uint32_t* lw0 = (const uint32_t*)&l0;
                const uint32_t* hw1 = (const uint32_t*)&h1;
                const uint32_t* lw1 = (const uint32_t*)&l1;
#pragma unroll
                for (int w = 0; w < 4; ++w) {
                    float2 a = __bfloat1622float2(*(const __nv_bfloat162*)&hw0[w]);
                    float2 b = __bfloat1622float2(*(const __nv_bfloat162*)&lw0[w]);
                    float2 c = __bfloat1622float2(*(const __nv_bfloat162*)&hw1[w]);
                    float2 d = __bfloat1622float2(*(const __nv_bfloat162*)&lw1[w]);
                    acc[w * 2 + 0] += (a.x + b.x) + (c.x + d.x);
                    acc[w * 2 + 1] += (a.y + b.y) + (c.y + d.y);
                }
            }
            for (; t < cnt; ++t) {
                int i0 = __shfl_sync(0xffffffffu, my, t);
                uint4 h0 = H[(size_t)i0 * 32 + lane];
                uint4 l0 = L[(size_t)i0 * 32 + lane];
                const uint32_t* hw0 = (const uint32_t*)&h0;
                const uint32_t* lw0 = (const uint32_t*)&l0;
#pragma unroll
                for (int w = 0; w < 4; ++w) {
                    float2 a = __bfloat1622float2(*(const __nv_bfloat162*)&hw0[w]);
                    float2 b = __bfloat1622float2(*(const __nv_bfloat162*)&lw0[w]);
                    acc[w * 2 + 0] += a.x + b.x;
                    acc[w * 2 + 1] += a.y + b.y;
                }
            }
        }
    }

    float scale = (end > start) ? (1.f / (float)(end - start)) : 0.f;
#pragma unroll
    for (int k = 0; k < 8; ++k) acc[k] *= scale;
    size_t rowOff = (size_t)node * DD;

    if (INBF == 0) {
        // lane covers cols lane*4 and 128+lane*4
#pragma unroll
        for (int half = 0; half < 2; ++half) {
            int col = half * 128 + lane * 4;
            __nv_bfloat16 h0 = __float2bfloat16(acc[half * 4 + 0]);
            __nv_bfloat16 h1 = __float2bfloat16(acc[half * 4 + 1]);
            __nv_bfloat16 h2 = __float2bfloat16(acc[half * 4 + 2]);
            __nv_bfloat16 h3 = __float2bfloat16(acc[half * 4 + 3]);
            __nv_bfloat162 hp0; hp0.x = h0; hp0.y = h1;
            __nv_bfloat162 hp1; hp1.x = h2; hp1.y = h3;
            __nv_bfloat162 lp0, lp1;
            lp0.x = __float2bfloat16(acc[half * 4 + 0] - __bfloat162float(h0));
            lp0.y = __float2bfloat16(acc[half * 4 + 1] - __bfloat162float(h1));
            lp1.x = __float2bfloat16(acc[half * 4 + 2] - __bfloat162float(h2));
            lp1.y = __float2bfloat16(acc[half * 4 + 3] - __bfloat162float(h3));
            *(__nv_bfloat162*)&oh[rowOff + col]     = hp0;
            *(__nv_bfloat162*)&oh[rowOff + col + 2] = hp1;
            *(__nv_bfloat162*)&ol[rowOff + col]     = lp0;
            *(__nv_bfloat162*)&ol[rowOff + col + 2] = lp1;
        }
    } else {
        // lane covers cols lane*8..lane*8+7; one uint4 store per array
        uint32_t hw[4], lw[4];
#pragma unroll
        for (int w = 0; w < 4; ++w) {
            __nv_bfloat16 h0 = __float2bfloat16(acc[w * 2 + 0]);
            __nv_bfloat16 h1 = __float2bfloat16(acc[w * 2 + 1]);
            __nv_bfloat162 hp; hp.x = h0; hp.y = h1;
            __nv_bfloat162 lp;
            lp.x = __float2bfloat16(acc[w * 2 + 0] - __bfloat162float(h0));
            lp.y = __float2bfloat16(acc[w * 2 + 1] - __bfloat162float(h1));
            hw[w] = *(uint32_t*)&hp;
            lw[w] = *(uint32_t*)&lp;
        }
        *(uint4*)&oh[rowOff + lane * 8] = make_uint4(hw[0], hw[1], hw[2], hw[3]);
        *(uint4*)&ol[rowOff + lane * 8] = make_uint4(lw[0], lw[1], lw[2], lw[3]);
    }
}

// ---------------- split-bf16 double GEMM via tensor cores -------------------
// C = A1@B1 + A2@B2 + bias; products Ahi@Bhi + Ahi@Blo + Alo@Bhi.
// 24 stages ordered chunk-major over 6 (A,B) products per K-chunk so adjacent
// products share the A tile: per chunk only 4 A loads (A1h, A1l, A2h, A2l).
// Separate A/B smem double buffers; grid is (2, rows) so the two column-block
// CTAs of one row-block are adjacent bids and share A tiles via L2.
#define G_BM 128
#define G_BN 128
#define G_BK 64
#define PADW 36                 // words per smem row (32 data + 4 pad)
#define NSTAGES 24              // 4 chunks * 6 products
#define BUF_WORDS (G_BM * PADW)             // 4608 words = 18432 B per buffer
#define GEMM_SMEM_BYTES (4 * BUF_WORDS * 4)    // 2 A + 2 B buffers = 73728

template <int RELU, int SPLIT>
__global__ void __launch_bounds__(256, 2) gemm_mma(
    const __nv_bfloat16* __restrict__ A1h, const __nv_bfloat16* __restrict__ A1l,
    const __nv_bfloat16* __restrict__ A2h, const __nv_bfloat16* __restrict__ A2l,
    const __nv_bfloat16* __restrict__ B1h, const __nv_bfloat16* __restrict__ B1l,
    const __nv_bfloat16* __restrict__ B2h, const __nv_bfloat16* __restrict__ B2l,
    const float* __restrict__ bias,
    float* __restrict__ Cf, __nv_bfloat16* __restrict__ Ch, __nv_bfloat16* __restrict__ Cl,
    int M)
{
    extern __shared__ uint32_t dsm[];
    uint32_t* AsW = dsm;                     // 2 buffers of BUF_WORDS
    uint32_t* BsW = dsm + 2 * BUF_WORDS;

    const int tid  = threadIdx.x;
    const int wid  = tid >> 5;
    const int lane = tid & 31;
    const int grp  = lane >> 2;      // 0..7
    const int tig  = lane & 3;       // 0..3
    const int wm   = (wid & 3) * 32; // warp M offset (4 warps)
    const int wn   = (wid >> 2) * 64;// warp N offset (2 warps)
    const int colBase = blockIdx.x * G_BN;   // grid.x = 2 -> colblocks adjacent
    const int rowBase = blockIdx.y * G_BM;

    float acc[2][8][4];
#pragma unroll
    for (int mi = 0; mi < 2; mi++)
#pragma unroll
        for (int nj = 0; nj < 8; nj++)
#pragma unroll
            for (int c = 0; c < 4; c++) acc[mi][nj][c] = 0.f;

    // stage decode: j = t%6 product within chunk, c = t/6 chunk
    //  aSel = {A1h,A1h,A1l,A2h,A2h,A2l}, bSel = {B1h,B1l,B1h,B2h,B2l,B2h}
    //  newA at j in {0,2,3,5}; aBuf parity = (#A-loads so far) & 1 = (4c+amap)&1
    auto load_stage = [&](int t) {
        const int j = t % 6, c = t / 6, kk = c * G_BK;
        const int ai = (j > 1) + (j > 2) + (j > 4);           // 0..3
        const int bi = ((j == 1) || (j == 4) ? 1 : 0) + (j >= 3 ? 2 : 0);
        const bool nA = (j != 1) && (j != 4);
        const int aBuf = (c * 4 + ai) & 1;
        const int bBuf = t & 1;
        const __nv_bfloat16* A;
        switch (ai) { case 0: A = A1h; break; case 1: A = A1l; break;
                      case 2: A = A2h; break; default: A = A2l; break; }
        const __nv_bfloat16* B;
        switch (bi) { case 0: B = B1h; break; case 1: B = B1l; break;
                      case 2: B = B2h; break; default: B = B2l; break; }
#pragma unroll
        for (int i = 0; i < 4; i++) {
            int id  = tid + i * 256;
            int row = id >> 3;        // 0..127
            int c16 = id & 7;         // 16B chunk within 128B row
            uint32_t so = (uint32_t)(row * (PADW * 2) + c16 * 8) * 2;  // bytes
            if (nA) {
                int grow = min(rowBase + row, M - 1);
                cp_async16(smem_u32(AsW) + aBuf * (BUF_WORDS * 4) + so,
                           A + (size_t)grow * DD + kk + c16 * 8);
            }
            cp_async16(smem_u32(BsW) + bBuf * (BUF_WORDS * 4) + so,
                       B + (size_t)(colBase + row) * DD + kk + c16 * 8);
        }
    };

    load_stage(0);
    asm volatile("cp.async.commit_group;\n");

    for (int t = 0; t < NSTAGES; ++t) {
        if (t + 1 < NSTAGES) {
            load_stage(t + 1);
            asm volatile("cp.async.commit_group;\n");
            asm volatile("cp.async.wait_group 1;\n");
        } else {
            asm volatile("cp.async.wait_group 0;\n");
        }
        __syncthreads();

        const int j = t % 6, c = t / 6;
        const int ai = (j > 1) + (j > 2) + (j > 4);
        const uint32_t* As32 = AsW + (((c * 4 + ai) & 1) ? BUF_WORDS : 0);
        const uint32_t* Bs32 = BsW + ((t & 1) ? BUF_WORDS : 0);

#pragma unroll
        for (int ks = 0; ks < 4; ++ks) {
            const int kw = ks * 8 + tig;   // word column (k/2)
            uint32_t af[2][4], bfr[8][2];
#pragma unroll
            for (int mi = 0; mi < 2; ++mi) {
                const int r = wm + mi * 16 + grp;
                af[mi][0] = As32[r * PADW + kw];
                af[mi][1] = As32[(r + 8) * PADW + kw];
                af[mi][2] = As32[r * PADW + kw + 4];
                af[mi][3] = As32[(r + 8) * PADW + kw + 4];
            }
#pragma unroll
            for (int nj = 0; nj < 8; ++nj) {
                const int n = wn + nj * 8 + grp;
                bfr[nj][0] = Bs32[n * PADW + kw];
                bfr[nj][1] = Bs32[n * PADW + kw + 4];
            }
#pragma unroll
            for (int mi = 0; mi < 2; ++mi)
#pragma unroll
                for (int nj = 0; nj < 8; ++nj)
                    mma_bf16(acc[mi][nj], af[mi], bfr[nj]);
        }
        __syncthreads();
    }

    // epilogue: SPLIT=1 -> write hi/lo bf16 planes only; SPLIT=0 -> fp32 out
#pragma unroll
    for (int mi = 0; mi < 2; ++mi) {
        const int rA = rowBase + wm + mi * 16 + grp;
#pragma unroll
        for (int nj = 0; nj < 8; ++nj) {
            const int col = colBase + wn + nj * 8 + tig * 2;
            const float bb0 = bias[col], bb1 = bias[col + 1];
            float v0 = acc[mi][nj][0] + bb0;
            float v1 = acc[mi][nj][1] + bb1;
            float v2 = acc[mi][nj][2] + bb0;
            float v3 = acc[mi][nj][3] + bb1;
            if (RELU) {
                v0 = fmaxf(v0, 0.f); v1 = fmaxf(v1, 0.f);
                v2 = fmaxf(v2, 0.f); v3 = fmaxf(v3, 0.f);
            }
            if (rA < M) {
                if (SPLIT) {
                    __nv_bfloat16 h0 = __float2bfloat16(v0), h1 = __float2bfloat16(v1);
                    __nv_bfloat162 hp; hp.x = h0; hp.y = h1;
                    __nv_bfloat162 lp;
                    lp.x = __float2bfloat16(v0 - __bfloat162float(h0));
                    lp.y = __float2bfloat16(v1 - __bfloat162float(h1));
                    *(__nv_bfloat162*)&Ch[(size_t)rA * DD + col] = hp;
                    *(__nv_bfloat162*)&Cl[(size_t)rA * DD + col] = lp;
                } else {
                    *(float2*)&Cf[(size_t)rA * DD + col] = make_float2(v0, v1);
                }
            }
            if (rA + 8 < M) {
                if (SPLIT) {
                    __nv_bfloat16 h2 = __float2bfloat16(v2), h3 = __float2bfloat16(v3);
                    __nv_bfloat162 hp; hp.x = h2; hp.y = h3;
                    __nv_bfloat162 lp;
                    lp.x = __float2bfloat16(v2 - __bfloat162float(h2));
                    lp.y = __float2bfloat16(v3 - __bfloat162float(h3));
                    *(__nv_bfloat162*)&Ch[(size_t)(rA + 8) * DD + col] = hp;
                    *(__nv_bfloat162*)&Cl[(size_t)(rA + 8) * DD + col] = lp;
                } else {
                    *(float2*)&Cf[(size_t)(rA + 8) * DD + col] = make_float2(v2, v3);
                }
            }
        }
    }
}

// ---------------- launch -----------------------------------------------------
extern "C" void kernel_launch(void* const* d_in, const int* in_sizes, int n_in,
                              void* d_out, int out_size) {
    const float* x     = (const float*)d_in[0];
    const int*   eidxW = (const int*)d_in[1];   // [2, E], int32 or int64 (auto-detected)
    const float* Wl1   = (const float*)d_in[2];
    const float* Wr1   = (const float*)d_in[3];
    const float* b1    = (const float*)d_in[4];
    const float* Wlin1 = (const float*)d_in[5];
    const float* blin1 = (const float*)d_in[6];
    const float* Wl2   = (const float*)d_in[7];
    const float* Wr2   = (const float*)d_in[8];
    const float* b2    = (const float*)d_in[9];
    const float* Wlin2 = (const float*)d_in[10];
    const float* blin2 = (const float*)d_in[11];
    float* out = (float*)d_out;

    float* b1c; cudaGetSymbolAddress((void**)&b1c, g_b1);
    float* b2c; cudaGetSymbolAddress((void**)&b2c, g_b2);
    __nv_bfloat16 *xh, *xl, *aggh, *aggl, *hh, *hl;
    cudaGetSymbolAddress((void**)&xh, g_xh);
    cudaGetSymbolAddress((void**)&xl, g_xl);
    cudaGetSymbolAddress((void**)&aggh, g_aggh);
    cudaGetSymbolAddress((void**)&aggl, g_aggl);
    cudaGetSymbolAddress((void**)&hh, g_hh);
    cudaGetSymbolAddress((void**)&hl, g_hl);
    __nv_bfloat16 *B1h, *B1l, *B2h, *B2l, *B3h, *B3l, *B4h, *B4l;
    cudaGetSymbolAddress((void**)&B1h, g_B1h);
    cudaGetSymbolAddress((void**)&B1l, g_B1l);
    cudaGetSymbolAddress((void**)&B2h, g_B2h);
    cudaGetSymbolAddress((void**)&B2l, g_B2l);
    cudaGetSymbolAddress((void**)&B3h, g_B3h);
    cudaGetSymbolAddress((void**)&B3l, g_B3l);
    cudaGetSymbolAddress((void**)&B4h, g_B4h);
    cudaGetSymbolAddress((void**)&B4l, g_B4l);

    cudaFuncSetAttribute(gemm_mma<1, 1>, cudaFuncAttributeMaxDynamicSharedMemorySize,
                         GEMM_SMEM_BYTES);
    cudaFuncSetAttribute(gemm_mma<0, 0>, cudaFuncAttributeMaxDynamicSharedMemorySize,
                         GEMM_SMEM_BYTES);

    // 0) decode edge index (dtype-agnostic); extract also zeroes deg/cursor
    detect_dtype<<<1, 1024>>>(eidxW);
    extract_edges<<<(EE + 255) / 256, 256>>>(eidxW);

    // 1) weight prep
    prep_weights<<<(DD * DD + 255) / 256, 256>>>(Wr1, Wlin1, b1, blin1, Wr2, Wlin2, b2, blin2);

    // 2) build CSR (by dst) once
    hist_kernel<<<(EE + 255) / 256, 256>>>();
    scanA<<<NBLK, SCAN_B>>>();
    scanB<<<1, 32>>>();
    scanC<<<(NN + 255) / 256, 256>>>();
    fill_csr<<<(EE + 255) / 256, 256>>>();

    // 3) remaining prep
    transpose_split<<<dim3(DD, 4), DD>>>(Wl1, Wl2);
    split_x<<<(int)(((size_t)NN * DD + 255) / 256), 256>>>(x);

    dim3 gemmGrid(DD / G_BN, (NN + G_BM - 1) / G_BM);   // (2, 782): colblocks adjacent
    const int aggBlocks = (NN + 7) / 8;

    // 4) layer 1
    aggregate_split<0><<<aggBlocks, 256>>>(x, nullptr, nullptr, aggh, aggl);
    gemm_mma<1, 1><<<gemmGrid, 256, GEMM_SMEM_BYTES>>>(aggh, aggl, xh, xl,
                                                       B1h, B1l, B2h, B2l,
                                                       b1c, nullptr, hh, hl, NN);

    // 5) layer 2
    aggregate_split<1><<<aggBlocks, 256>>>(nullptr, hh, hl, aggh, aggl);
    gemm_mma<0, 0><<<gemmGrid, 256, GEMM_SMEM_BYTES>>>(aggh, aggl, hh, hl,
                                                       B3h, B3l, B4h, B4l,
                                                       b2c, out, nullptr, nullptr, NN);
}

// round 11
// speedup vs baseline: 2.2735x; 1.0409x over previous
#include <cuda_runtime.h>
#include <cuda_bf16.h>
#include <cstdint>

#define NN 100000
#define EE 1600000
#define DD 256
#define SCAN_B 1024
#define NBLK ((NN + SCAN_B - 1) / SCAN_B)   // 98

// ---------------- scratch (device globals; no allocations allowed) ----------
__device__ __nv_bfloat16 g_xh[(size_t)NN * DD];
__device__ __nv_bfloat16 g_xl[(size_t)NN * DD];
__device__ __nv_bfloat16 g_aggh[(size_t)NN * DD];
__device__ __nv_bfloat16 g_aggl[(size_t)NN * DD];
__device__ __nv_bfloat16 g_hh[(size_t)NN * DD];
__device__ __nv_bfloat16 g_hl[(size_t)NN * DD];
__device__ int   g_src[EE];
__device__ int   g_dst[EE];
__device__ int   g_is64;
__device__ int   g_deg[NN];
__device__ int   g_scan[NN];
__device__ int   g_rowptr[NN + 1];
__device__ int   g_cursor[NN];
__device__ int   g_csr_src[EE];
__device__ int   g_bsum[NBLK];
__device__ int   g_boff[NBLK];
__device__ float g_b1[DD];
__device__ float g_b2[DD];
// transposed + split B matrices: layout [n][k] (n-major), bf16
__device__ __nv_bfloat16 g_B1h[DD * DD], g_B1l[DD * DD];   // Wl1
__device__ __nv_bfloat16 g_B2h[DD * DD], g_B2l[DD * DD];   // Wr1+Wlin1
__device__ __nv_bfloat16 g_B3h[DD * DD], g_B3l[DD * DD];   // Wl2
__device__ __nv_bfloat16 g_B4h[DD * DD], g_B4l[DD * DD];   // Wr2+Wlin2

// ---------------- PTX helpers ------------------------------------------------
__device__ __forceinline__ void mma_bf16(float* d, const uint32_t* a, const uint32_t* b) {
    asm volatile(
        "mma.sync.aligned.m16n8k16.row.col.f32.bf16.bf16.f32 "
        "{%0,%1,%2,%3}, {%4,%5,%6,%7}, {%8,%9}, {%0,%1,%2,%3};\n"
        : "+f"(d[0]), "+f"(d[1]), "+f"(d[2]), "+f"(d[3])
        : "r"(a[0]), "r"(a[1]), "r"(a[2]), "r"(a[3]), "r"(b[0]), "r"(b[1]));
}

__device__ __forceinline__ void ldmatrix_x4(uint32_t& r0, uint32_t& r1,
                                            uint32_t& r2, uint32_t& r3, uint32_t addr) {
    asm volatile("ldmatrix.sync.aligned.m8n8.x4.shared.b16 {%0,%1,%2,%3}, [%4];"
                 : "=r"(r0), "=r"(r1), "=r"(r2), "=r"(r3) : "r"(addr));
}

__device__ __forceinline__ void cp_async16(uint32_t saddr, const void* gaddr) {
    asm volatile("cp.async.cg.shared.global [%0], [%1], 16;\n" :: "r"(saddr), "l"(gaddr));
}

__device__ __forceinline__ uint32_t smem_u32(const void* p) {
    return (uint32_t)__cvta_generic_to_shared(p);
}

// ---------------- edge dtype detection + extraction -------------------------
__global__ void detect_dtype(const int* __restrict__ w) {
    __shared__ int nz;
    if (threadIdx.x == 0) nz = 0;
    __syncthreads();
    int v = w[2 * threadIdx.x + 1];
    if (v != 0) atomicOr(&nz, 1);
    __syncthreads();
    if (threadIdx.x == 0) g_is64 = (nz == 0) ? 1 : 0;
}

// also zeroes deg/cursor (fused; no dependency within this kernel)
__global__ void extract_edges(const int* __restrict__ w) {
    int e = blockIdx.x * blockDim.x + threadIdx.x;
    if (e < NN) { g_deg[e] = 0; g_cursor[e] = 0; }
    if (e >= EE) return;
    int s, d;
    if (g_is64) {
        s = w[2 * (size_t)e];
        d = w[2 * ((size_t)EE + e)];
    } else {
        s = w[e];
        d = w[EE + e];
    }
    s = min(max(s, 0), NN - 1);
    d = min(max(d, 0), NN - 1);
    g_src[e] = s;
    g_dst[e] = d;
}

// ---------------- prep: combine + transpose + split (one kernel) ------------
// transpose [k][n] -> [n][k], split into hi/lo bf16; matrices 1/3 combine
// Wr+Wlin inline; biases folded in at k==0.
__global__ void transpose_split(const float* __restrict__ Wl1,
                                const float* __restrict__ Wr1, const float* __restrict__ Wlin1,
                                const float* __restrict__ Wl2,
                                const float* __restrict__ Wr2, const float* __restrict__ Wlin2,
                                const float* __restrict__ b1,  const float* __restrict__ blin1,
                                const float* __restrict__ b2,  const float* __restrict__ blin2) {
    int k = blockIdx.x, n = threadIdx.x;
    float v;
    __nv_bfloat16 *dh, *dl;
    switch (blockIdx.y) {
        case 0:  v = Wl1[k * DD + n];                         dh = g_B1h; dl = g_B1l; break;
        case 1:  v = Wr1[k * DD + n] + Wlin1[k * DD + n];     dh = g_B2h; dl = g_B2l; break;
        case 2:  v = Wl2[k * DD + n];                         dh = g_B3h; dl = g_B3l; break;
        default: v = Wr2[k * DD + n] + Wlin2[k * DD + n];     dh = g_B4h; dl = g_B4l; break;
    }
    __nv_bfloat16 hi = __float2bfloat16(v);
    float lo = v - __bfloat162float(hi);
    dh[n * DD + k] = hi;
    dl[n * DD + k] = __float2bfloat16(lo);
    if (k == 0) {
        if (blockIdx.y == 1) g_b1[n] = b1[n] + blin1[n];
        if (blockIdx.y == 3) g_b2[n] = b2[n] + blin2[n];
    }
}

__global__ void split_x(const float* __restrict__ x) {
    size_t i = (size_t)blockIdx.x * blockDim.x + threadIdx.x;
    if (i >= (size_t)NN * DD) return;
    float v = x[i];
    __nv_bfloat16 hi = __float2bfloat16(v);
    float lo = v - __bfloat162float(hi);
    g_xh[i] = hi;
    g_xl[i] = __float2bfloat16(lo);
}

// ---------------- CSR build --------------------------------------------------
__global__ void hist_kernel() {
    int e = blockIdx.x * blockDim.x + threadIdx.x;
    if (e < EE) atomicAdd(&g_deg[g_dst[e]], 1);
}

__global__ void scanA() {
    __shared__ int sh[SCAN_B];
    int i = blockIdx.x * SCAN_B + threadIdx.x;
    sh[threadIdx.x] = (i < NN) ? g_deg[i] : 0;
    __syncthreads();
    for (int off = 1; off < SCAN_B; off <<= 1) {
        int t = (threadIdx.x >= off) ? sh[threadIdx.x - off] : 0;
        __syncthreads();
        sh[threadIdx.x] += t;
        __syncthreads();
    }
    if (i < NN) g_scan[i] = sh[threadIdx.x];
    if (threadIdx.x == SCAN_B - 1) g_bsum[blockIdx.x] = sh[SCAN_B - 1];
}

__global__ void scanB() {
    if (threadIdx.x == 0 && blockIdx.x == 0) {
        int run = 0;
        for (int b = 0; b < NBLK; b++) { int t = g_bsum[b]; g_boff[b] = run; run += t; }
    }
}

__global__ void scanC() {
    int i = blockIdx.x * blockDim.x + threadIdx.x;
    if (i < NN) g_rowptr[i] = g_scan[i] - g_deg[i] + g_boff[i / SCAN_B];
    if (i == 0) g_rowptr[NN] = EE;
}

__global__ void fill_csr() {
    int e = blockIdx.x * blockDim.x + threadIdx.x;
    if (e < EE) {
        int d = g_dst[e];
        int pos = g_rowptr[d] + atomicAdd(&g_cursor[d], 1);
        g_csr_src[pos] = g_src[e];
    }
}

// ---------------- mean aggregation: one WARP per dst node -------------------
// INBF=0: gather fp32 feat rows.  INBF=1: gather bf16 hi/lo rows, v = hi+lo.
template <int INBF>
__global__ void __launch_bounds__(256) aggregate_split(
    const float* __restrict__ feat,
    const __nv_bfloat16* __restrict__ fh, const __nv_bfloat16* __restrict__ fl,
    __nv_bfloat16* __restrict__ oh, __nv_bfloat16* __restrict__ ol) {
    int node = blockIdx.x * 8 + (threadIdx.x >> 5);
    int lane = threadIdx.x & 31;
    if (node >= NN) return;
    int start = g_rowptr[node];
    int end   = g_rowptr[node + 1];

    float acc[8] = {0.f, 0.f, 0.f, 0.f, 0.f, 0.f, 0.f, 0.f};

    if (INBF == 0) {
        const float4* f4 = (const float4*)feat;  // 64 float4 per row
        for (int base = start; base < end; base += 32) {
            int cnt = min(32, end - base);
            int my = (base + lane < end) ? g_csr_src[base + lane] : 0;
            int t = 0;
            for (; t + 4 <= cnt; t += 4) {
                int i0 = __shfl_sync(0xffffffffu, my, t);
                int i1 = __shfl_sync(0xffffffffu, my, t + 1);
                int i2 = __shfl_sync(0xffffffffu, my, t + 2);
                int i3 = __shfl_sync(0xffffffffu, my, t + 3);
                const float4* p0 = f4 + (size_t)i0 * 64;
                const float4* p1 = f4 + (size_t)i1 * 64;
                const float4* p2 = f4 + (size_t)i2 * 64;
                const float4* p3 = f4 + (size_t)i3 * 64;
                float4 v00 = p0[lane], v01 = p0[lane + 32];
                float4 v10 = p1[lane], v11 = p1[lane + 32];
                float4 v20 = p2[lane], v21 = p2[lane + 32];
                float4 v30 = p3[lane], v31 = p3[lane + 32];
                acc[0] += (v00.x + v10.x) + (v20.x + v30.x);
                acc[1] += (v00.y + v10.y) + (v20.y + v30.y);
                acc[2] += (v00.z + v10.z) + (v20.z + v30.z);
                acc[3] += (v00.w + v10.w) + (v20.w + v30.w);
                acc[4] += (v01.x + v11.x) + (v21.x + v31.x);
                acc[5] += (v01.y + v11.y) + (v21.y + v31.y);
                acc[6] += (v01.z + v11.z) + (v21.z + v31.z);
                acc[7] += (v01.w + v11.w) + (v21.w + v31.w);
            }
            for (; t < cnt; ++t) {
                int i0 = __shfl_sync(0xffffffffu, my, t);
                const float4* p0 = f4 + (size_t)i0 * 64;
                float4 v00 = p0[lane], v01 = p0[lane + 32];
                acc[0] += v00.x; acc[1] += v00.y; acc[2] += v00.z; acc[3] += v00.w;
                acc[4] += v01.x; acc[5] += v01.y; acc[6] += v01.z; acc[7] += v01.w;
            }
        }
    } else {
        const uint4* H = (const uint4*)fh;   // 32 uint4 (8 bf16 each) per row
        const uint4* L = (const uint4*)fl;
        for (int base = start; base < end; base += 32) {
            int cnt = min(32, end - base);
            int my = (base + lane < end) ? g_csr_src[base + lane] : 0;
            int t = 0;
            for (; t + 2 <= cnt; t += 2) {
                int i0 = __shfl_sync(0xffffffffu, my, t);
                int i1 = __shfl_sync(0xffffffffu, my, t + 1);
                uint4 h0 = H[(size_t)i0 * 32 + lane];
                uint4 l0 = L[(size_t)i0 * 32 + lane];
                uint4 h1 = H[(size_t)i1 * 32 + lane];
                uint4 l1 = L[(size_t)i1 * 32 + lane];
                const uint32_t* hw0 = (const uint32_t*)&h0;
                const uint32_t* lw0 = (const uint32_t*)&l0;
                const uint32_t* hw1 = (const uint32_t*)&h1;
                const uint32_t* lw1 = (const uint32_t*)&l1;
#pragma unroll
                for (int w = 0; w < 4; ++w) {
                    float2 a = __bfloat1622float2(*(const __nv_bfloat162*)&hw0[w]);
                    float2 b = __bfloat1622float2(*(const __nv_bfloat162*)&lw0[w]);
                    float2 c = __bfloat1622float2(*(const __nv_bfloat162*)&hw1[w]);
                    float2 d = __bfloat1622float2(*(const __nv_bfloat162*)&lw1[w]);
                    acc[w * 2 + 0] += (a.x + b.x) + (c.x + d.x);
                    acc[w * 2 + 1] += (a.y + b.y) + (c.y + d.y);
                }
            }
            for (; t < cnt; ++t) {
                int i0 = __shfl_sync(0xffffffffu, my, t);
                uint4 h0 = H[(size_t)i0 * 32 + lane];
                uint4 l0 = L[(size_t)i0 * 32 + lane];
                const uint32_t* hw0 = (const uint32_t*)&h0;
                const uint32_t* lw0 = (const uint32_t*)&l0;
#pragma unroll
                for (int w = 0; w < 4; ++w) {
                    float2 a = __bfloat1622float2(*(const __nv_bfloat162*)&hw0[w]);
                    float2 b = __bfloat1622float2(*(const __nv_bfloat162*)&lw0[w]);
                    acc[w * 2 + 0] += a.x + b.x;
                    acc[w * 2 + 1] += a.y + b.y;
                }
            }
        }
    }

    float scale = (end > start) ? (1.f / (float)(end - start)) : 0.f;
#pragma unroll
    for (int k = 0; k < 8; ++k) acc[k] *= scale;
    size_t rowOff = (size_t)node * DD;

    if (INBF == 0) {
        // lane covers cols lane*4 and 128+lane*4
#pragma unroll
        for (int half = 0; half < 2; ++half) {
            int col = half * 128 + lane * 4;
            __nv_bfloat16 h0 = __float2bfloat16(acc[half * 4 + 0]);
            __nv_bfloat16 h1 = __float2bfloat16(acc[half * 4 + 1]);
            __nv_bfloat16 h2 = __float2bfloat16(acc[half * 4 + 2]);
            __nv_bfloat16 h3 = __float2bfloat16(acc[half * 4 + 3]);
            __nv_bfloat162 hp0; hp0.x = h0; hp0.y = h1;
            __nv_bfloat162 hp1; hp1.x = h2; hp1.y = h3;
            __nv_bfloat162 lp0, lp1;
            lp0.x = __float2bfloat16(acc[half * 4 + 0] - __bfloat162float(h0));
            lp0.y = __float2bfloat16(acc[half * 4 + 1] - __bfloat162float(h1));
            lp1.x = __float2bfloat16(acc[half * 4 + 2] - __bfloat162float(h2));
            lp1.y = __float2bfloat16(acc[half * 4 + 3] - __bfloat162float(h3));
            *(__nv_bfloat162*)&oh[rowOff + col]     = hp0;
            *(__nv_bfloat162*)&oh[rowOff + col + 2] = hp1;
            *(__nv_bfloat162*)&ol[rowOff + col]     = lp0;
            *(__nv_bfloat162*)&ol[rowOff + col + 2] = lp1;
        }
    } else {
        // lane covers cols lane*8..lane*8+7; one uint4 store per array
        uint32_t hw[4], lw[4];
#pragma unroll
        for (int w = 0; w < 4; ++w) {
            __nv_bfloat16 h0 = __float2bfloat16(acc[w * 2 + 0]);
            __nv_bfloat16 h1 = __float2bfloat16(acc[w * 2 + 1]);
            __nv_bfloat162 hp; hp.x = h0; hp.y = h1;
            __nv_bfloat162 lp;
            lp.x = __float2bfloat16(acc[w * 2 + 0] - __bfloat162float(h0));
            lp.y = __float2bfloat16(acc[w * 2 + 1] - __bfloat162float(h1));
            hw[w] = *(uint32_t*)&hp;
            lw[w] = *(uint32_t*)&lp;
        }
        *(uint4*)&oh[rowOff + lane * 8] = make_uint4(hw[0], hw[1], hw[2], hw[3]);
        *(uint4*)&ol[rowOff + lane * 8] = make_uint4(lw[0], lw[1], lw[2], lw[3]);
    }
}

// ---------------- split-bf16 double GEMM via tensor cores -------------------
// C = A1@B1 + A2@B2 + bias; products Ahi@Bhi + Ahi@Blo + Alo@Bhi.
// 24 stages chunk-major over 6 products per K-chunk (A loaded 4x/chunk).
// Fragments loaded via ldmatrix.m8n8.x4 (conflict-free with PADW=36 rows).
// grid (2, rows): the two column-block CTAs per row-block share A via L2.
#define G_BM 128
#define G_BN 128
#define G_BK 64
#define PADW 36                 // words per smem row (32 data + 4 pad)
#define NSTAGES 24              // 4 chunks * 6 products
#define BUF_WORDS (G_BM * PADW)             // 4608 words = 18432 B per buffer
#define BUF_BYTES (BUF_WORDS * 4)
#define GEMM_SMEM_BYTES (4 * BUF_BYTES)     // 2 A + 2 B buffers = 73728

template <int RELU, int SPLIT>
__global__ void __launch_bounds__(256, 2) gemm_mma(
    const __nv_bfloat16* __restrict__ A1h, const __nv_bfloat16* __restrict__ A1l,
    const __nv_bfloat16* __restrict__ A2h, const __nv_bfloat16* __restrict__ A2l,
    const __nv_bfloat16* __restrict__ B1h, const __nv_bfloat16* __restrict__ B1l,
    const __nv_bfloat16* __restrict__ B2h, const __nv_bfloat16* __restrict__ B2l,
    const float* __restrict__ bias,
    float* __restrict__ Cf, __nv_bfloat16* __restrict__ Ch, __nv_bfloat16* __restrict__ Cl,
    int M)
{
    extern __shared__ uint32_t dsm[];
    uint32_t* AsW = dsm;                     // 2 buffers of BUF_WORDS
    uint32_t* BsW = dsm + 2 * BUF_WORDS;

    const int tid  = threadIdx.x;
    const int wid  = tid >> 5;
    const int lane = tid & 31;
    const int grp  = lane >> 2;      // 0..7
    const int tig  = lane & 3;       // 0..3
    const int wm   = (wid & 3) * 32; // warp M offset (4 warps)
    const int wn   = (wid >> 2) * 64;// warp N offset (2 warps)
    const int colBase = blockIdx.x * G_BN;   // grid.x = 2 -> colblocks adjacent
    const int rowBase = blockIdx.y * G_BM;

    const uint32_t aSm = smem_u32(AsW);
    const uint32_t bSm = smem_u32(BsW);
    // ldmatrix per-lane byte offsets (within a buffer), before mi/nj/ks terms:
    //  A: lane L -> row wm + (L&15), word (L>>4)*4
    const uint32_t aLdOff = (uint32_t)((wm + (lane & 15)) * PADW + (lane >> 4) * 4) * 4;
    //  B: lane L -> row wn + ((L>>4)<<3) + (L&7), word ((L>>3)&1)*4
    const uint32_t bLdOff = (uint32_t)((wn + ((lane >> 4) << 3) + (lane & 7)) * PADW
                                       + ((lane >> 3) & 1) * 4) * 4;

    float acc[2][8][4];
#pragma unroll
    for (int mi = 0; mi < 2; mi++)
#pragma unroll
        for (int nj = 0; nj < 8; nj++)
#pragma unroll
            for (int c = 0; c < 4; c++) acc[mi][nj][c] = 0.f;

    // stage decode: j = t%6 product within chunk, c = t/6 chunk
    //  aSel = {A1h,A1h,A1l,A2h,A2h,A2l}, bSel = {B1h,B1l,B1h,B2h,B2l,B2h}
    //  newA at j in {0,2,3,5}; aBuf parity = (#A-loads so far) & 1 = (4c+ai)&1
    auto load_stage = [&](int t) {
        const int j = t % 6, c = t / 6, kk = c * G_BK;
        const int ai = (j > 1) + (j > 2) + (j > 4);           // 0..3
        const int bi = ((j == 1) || (j == 4) ? 1 : 0) + (j >= 3 ? 2 : 0);
        const bool nA = (j != 1) && (j != 4);
        const int aBuf = (c * 4 + ai) & 1;
        const int bBuf = t & 1;
        const __nv_bfloat16* A;
        switch (ai) { case 0: A = A1h; break; case 1: A = A1l; break;
                      case 2: A = A2h; break; default: A = A2l; break; }
        const __nv_bfloat16* B;
        switch (bi) { case 0: B = B1h; break; case 1: B = B1l; break;
                      case 2: B = B2h; break; default: B = B2l; break; }
#pragma unroll
        for (int i = 0; i < 4; i++) {
            int id  = tid + i * 256;
            int row = id >> 3;        // 0..127
            int c16 = id & 7;         // 16B chunk within 128B row
            uint32_t so = (uint32_t)(row * (PADW * 2) + c16 * 8) * 2;  // bytes
            if (nA) {
                int grow = min(rowBase + row, M - 1);
                cp_async16(aSm + aBuf * BUF_BYTES + so,
                           A + (size_t)grow * DD + kk + c16 * 8);
            }
            cp_async16(bSm + bBuf * BUF_BYTES + so,
                       B + (size_t)(colBase + row) * DD + kk + c16 * 8);
        }
    };

    load_stage(0);
    asm volatile("cp.async.commit_group;\n");

    for (int t = 0; t < NSTAGES; ++t) {
        if (t + 1 < NSTAGES) {
            load_stage(t + 1);
            asm volatile("cp.async.commit_group;\n");
            asm volatile("cp.async.wait_group 1;\n");
        } else {
            asm volatile("cp.async.wait_group 0;\n");
        }
        __syncthreads();

        const int j = t % 6, c = t / 6;
        const int ai = (j > 1) + (j > 2) + (j > 4);
        const uint32_t aBase = aSm + (((c * 4 + ai) & 1) ? BUF_BYTES : 0) + aLdOff;
        const uint32_t bBase = bSm + ((t & 1) ? BUF_BYTES : 0) + bLdOff;

#pragma unroll
        for (int ks = 0; ks < 4; ++ks) {
            uint32_t af[2][4], bfr[8][2];
            // A fragments: one ldmatrix.x4 per mi (tiles: rows, rows+8, +4w, +4w rows+8)
#pragma unroll
            for (int mi = 0; mi < 2; ++mi)
                ldmatrix_x4(af[mi][0], af[mi][1], af[mi][2], af[mi][3],
                            aBase + mi * (16 * PADW * 4) + ks * 32);
            // B fragments: one ldmatrix.x4 per nj-pair
#pragma unroll
            for (int p = 0; p < 4; ++p)
                ldmatrix_x4(bfr[2 * p][0], bfr[2 * p][1], bfr[2 * p + 1][0], bfr[2 * p + 1][1],
                            bBase + p * (16 * PADW * 4) + ks * 32);
#pragma unroll
            for (int mi = 0; mi < 2; ++mi)
#pragma unroll
                for (int nj = 0; nj < 8; ++nj)
                    mma_bf16(acc[mi][nj], af[mi], bfr[nj]);
        }
        __syncthreads();
    }

    // epilogue: SPLIT=1 -> write hi/lo bf16 planes only; SPLIT=0 -> fp32 out
#pragma unroll
    for (int mi = 0; mi < 2; ++mi) {
        const int rA = rowBase + wm + mi * 16 + grp;
#pragma unroll
        for (int nj = 0; nj < 8; ++nj) {
            const int col = colBase + wn + nj * 8 + tig * 2;
            const float bb0 = bias[col], bb1 = bias[col + 1];
            float v0 = acc[mi][nj][0] + bb0;
            float v1 = acc[mi][nj][1] + bb1;
            float v2 = acc[mi][nj][2] + bb0;
            float v3 = acc[mi][nj][3] + bb1;
            if (RELU) {
                v0 = fmaxf(v0, 0.f); v1 = fmaxf(v1, 0.f);
                v2 = fmaxf(v2, 0.f); v3 = fmaxf(v3, 0.f);
            }
            if (rA < M) {
                if (SPLIT) {
                    __nv_bfloat16 h0 = __float2bfloat16(v0), h1 = __float2bfloat16(v1);
                    __nv_bfloat162 hp; hp.x = h0; hp.y = h1;
                    __nv_bfloat162 lp;
                    lp.x = __float2bfloat16(v0 - __bfloat162float(h0));
                    lp.y = __float2bfloat16(v1 - __bfloat162float(h1));
                    *(__nv_bfloat162*)&Ch[(size_t)rA * DD + col] = hp;
                    *(__nv_bfloat162*)&Cl[(size_t)rA * DD + col] = lp;
                } else {
                    *(float2*)&Cf[(size_t)rA * DD + col] = make_float2(v0, v1);
                }
            }
            if (rA + 8 < M) {
                if (SPLIT) {
                    __nv_bfloat16 h2 = __float2bfloat16(v2), h3 = __float2bfloat16(v3);
                    __nv_bfloat162 hp; hp.x = h2; hp.y = h3;
                    __nv_bfloat162 lp;
                    lp.x = __float2bfloat16(v2 - __bfloat162float(h2));
                    lp.y = __float2bfloat16(v3 - __bfloat162float(h3));
                    *(__nv_bfloat162*)&Ch[(size_t)(rA + 8) * DD + col] = hp;
                    *(__nv_bfloat162*)&Cl[(size_t)(rA + 8) * DD + col] = lp;
                } else {
                    *(float2*)&Cf[(size_t)(rA + 8) * DD + col] = make_float2(v2, v3);
                }
            }
        }
    }
}

// ---------------- launch -----------------------------------------------------
extern "C" void kernel_launch(void* const* d_in, const int* in_sizes, int n_in,
                              void* d_out, int out_size) {
    const float* x     = (const float*)d_in[0];
    const int*   eidxW = (const int*)d_in[1];   // [2, E], int32 or int64 (auto-detected)
    const float* Wl1   = (const float*)d_in[2];
    const float* Wr1   = (const float*)d_in[3];
    const float* b1    = (const float*)d_in[4];
    const float* Wlin1 = (const float*)d_in[5];
    const float* blin1 = (const float*)d_in[6];
    const float* Wl2   = (const float*)d_in[7];
    const float* Wr2   = (const float*)d_in[8];
    const float* b2    = (const float*)d_in[9];
    const float* Wlin2 = (const float*)d_in[10];
    const float* blin2 = (const float*)d_in[11];
    float* out = (float*)d_out;

    float* b1c; cudaGetSymbolAddress((void**)&b1c, g_b1);
    float* b2c; cudaGetSymbolAddress((void**)&b2c, g_b2);
    __nv_bfloat16 *xh, *xl, *aggh, *aggl, *hh, *hl;
    cudaGetSymbolAddress((void**)&xh, g_xh);
    cudaGetSymbolAddress((void**)&xl, g_xl);
    cudaGetSymbolAddress((void**)&aggh, g_aggh);
    cudaGetSymbolAddress((void**)&aggl, g_aggl);
    cudaGetSymbolAddress((void**)&hh, g_hh);
    cudaGetSymbolAddress((void**)&hl, g_hl);
    __nv_bfloat16 *B1h, *B1l, *B2h, *B2l, *B3h, *B3l, *B4h, *B4l;
    cudaGetSymbolAddress((void**)&B1h, g_B1h);
    cudaGetSymbolAddress((void**)&B1l, g_B1l);
    cudaGetSymbolAddress((void**)&B2h, g_B2h);
    cudaGetSymbolAddress((void**)&B2l, g_B2l);
    cudaGetSymbolAddress((void**)&B3h, g_B3h);
    cudaGetSymbolAddress((void**)&B3l, g_B3l);
    cudaGetSymbolAddress((void**)&B4h, g_B4h);
    cudaGetSymbolAddress((void**)&B4l, g_B4l);

    cudaFuncSetAttribute(gemm_mma<1, 1>, cudaFuncAttributeMaxDynamicSharedMemorySize,
                         GEMM_SMEM_BYTES);
    cudaFuncSetAttribute(gemm_mma<0, 0>, cudaFuncAttributeMaxDynamicSharedMemorySize,
                         GEMM_SMEM_BYTES);

    // 0) decode edge index (dtype-agnostic); extract also zeroes deg/cursor
    detect_dtype<<<1, 1024>>>(eidxW);
    extract_edges<<<(EE + 255) / 256, 256>>>(eidxW);

    // 1) build CSR (by dst) once
    hist_kernel<<<(EE + 255) / 256, 256>>>();
    scanA<<<NBLK, SCAN_B>>>();
    scanB<<<1, 32>>>();
    scanC<<<(NN + 255) / 256, 256>>>();
    fill_csr<<<(EE + 255) / 256, 256>>>();

    // 2) weight + feature prep (combine/transpose/split fused)
    transpose_split<<<dim3(DD, 4), DD>>>(Wl1, Wr1, Wlin1, Wl2, Wr2, Wlin2,
                                         b1, blin1, b2, blin2);
    split_x<<<(int)(((size_t)NN * DD + 255) / 256), 256>>>(x);

    dim3 gemmGrid(DD / G_BN, (NN + G_BM - 1) / G_BM);   // (2, 782): colblocks adjacent
    const int aggBlocks = (NN + 7) / 8;

    // 3) layer 1
    aggregate_split<0><<<aggBlocks, 256>>>(x, nullptr, nullptr, aggh, aggl);
    gemm_mma<1, 1><<<gemmGrid, 256, GEMM_SMEM_BYTES>>>(aggh, aggl, xh, xl,
                                                       B1h, B1l, B2h, B2l,
                                                       b1c, nullptr, hh, hl, NN);

    // 4) layer 2
    aggregate_split<1><<<aggBlocks, 256>>>(nullptr, hh, hl, aggh, aggl);
    gemm_mma<0, 0><<<gemmGrid, 256, GEMM_SMEM_BYTES>>>(aggh, aggl, hh, hl,
                                                       B3h, B3l, B4h, B4l,
                                                       b2c, out, nullptr, nullptr, NN);
}

// round 12
// speedup vs baseline: 2.3043x; 1.0135x over previous
#include <cuda_runtime.h>
#include <cuda_bf16.h>
#include <cstdint>

#define NN 100000
#define EE 1600000
#define DD 256
#define SCAN_B 1024
#define NBLK ((NN + SCAN_B - 1) / SCAN_B)   // 98

// ---------------- scratch (device globals; no allocations allowed) ----------
__device__ __nv_bfloat16 g_xh[(size_t)NN * DD];
__device__ __nv_bfloat16 g_xl[(size_t)NN * DD];
__device__ __nv_bfloat16 g_aggh[(size_t)NN * DD];
__device__ __nv_bfloat16 g_aggl[(size_t)NN * DD];
__device__ __nv_bfloat16 g_hh[(size_t)NN * DD];
__device__ __nv_bfloat16 g_hl[(size_t)NN * DD];
__device__ int   g_src[EE];
__device__ int   g_dst[EE];
__device__ int   g_deg[NN];
__device__ int   g_scan[NN];
__device__ int   g_rowptr[NN + 1];
__device__ int   g_cursor[NN];
__device__ int   g_csr_src[EE];
__device__ int   g_bsum[NBLK];
__device__ int   g_boff[NBLK];
__device__ float g_b1[DD];
__device__ float g_b2[DD];
// transposed + split B matrices: layout [n][k] (n-major), bf16
__device__ __nv_bfloat16 g_B1h[DD * DD], g_B1l[DD * DD];   // Wl1
__device__ __nv_bfloat16 g_B2h[DD * DD], g_B2l[DD * DD];   // Wr1+Wlin1
__device__ __nv_bfloat16 g_B3h[DD * DD], g_B3l[DD * DD];   // Wl2
__device__ __nv_bfloat16 g_B4h[DD * DD], g_B4l[DD * DD];   // Wr2+Wlin2

// ---------------- PTX helpers ------------------------------------------------
__device__ __forceinline__ void mma_bf16(float* d, const uint32_t* a, const uint32_t* b) {
    asm volatile(
        "mma.sync.aligned.m16n8k16.row.col.f32.bf16.bf16.f32 "
        "{%0,%1,%2,%3}, {%4,%5,%6,%7}, {%8,%9}, {%0,%1,%2,%3};\n"
        : "+f"(d[0]), "+f"(d[1]), "+f"(d[2]), "+f"(d[3])
        : "r"(a[0]), "r"(a[1]), "r"(a[2]), "r"(a[3]), "r"(b[0]), "r"(b[1]));
}

__device__ __forceinline__ void ldmatrix_x4(uint32_t& r0, uint32_t& r1,
                                            uint32_t& r2, uint32_t& r3, uint32_t addr) {
    asm volatile("ldmatrix.sync.aligned.m8n8.x4.shared.b16 {%0,%1,%2,%3}, [%4];"
                 : "=r"(r0), "=r"(r1), "=r"(r2), "=r"(r3) : "r"(addr));
}

__device__ __forceinline__ void cp_async16(uint32_t saddr, const void* gaddr) {
    asm volatile("cp.async.cg.shared.global [%0], [%1], 16;\n" :: "r"(saddr), "l"(gaddr));
}

__device__ __forceinline__ uint32_t smem_u32(const void* p) {
    return (uint32_t)__cvta_generic_to_shared(p);
}

// ---------------- counters init ----------------------------------------------
__global__ void zero_counts() {
    int i = blockIdx.x * blockDim.x + threadIdx.x;
    if (i < NN) { g_deg[i] = 0; g_cursor[i] = 0; }
}

// ---------------- edge extraction + histogram (fused) ------------------------
// Per-block dtype detection: if edge_index is int64 (values < 1e5), the first
// 1024 odd 32-bit words are all zero high-halves; if int32, they are random
// edge indices (P(all zero) ~ 0). 4KB of L2-resident reads per block.
__global__ void extract_hist(const int* __restrict__ w) {
    __shared__ int nz;
    if (threadIdx.x == 0) nz = 0;
    __syncthreads();
    for (int i = threadIdx.x; i < 1024; i += blockDim.x)
        if (w[2 * i + 1] != 0) { nz = 1; break; }
    __syncthreads();
    const int is64 = (nz == 0);

    int e = blockIdx.x * blockDim.x + threadIdx.x;
    if (e >= EE) return;
    int s, d;
    if (is64) {
        s = w[2 * (size_t)e];
        d = w[2 * ((size_t)EE + e)];
    } else {
        s = w[e];
        d = w[EE + e];
    }
    s = min(max(s, 0), NN - 1);
    d = min(max(d, 0), NN - 1);
    g_src[e] = s;
    g_dst[e] = d;
    atomicAdd(&g_deg[d], 1);
}

// ---------------- prep: combine + transpose + split (one kernel) ------------
__global__ void transpose_split(const float* __restrict__ Wl1,
                                const float* __restrict__ Wr1, const float* __restrict__ Wlin1,
                                const float* __restrict__ Wl2,
                                const float* __restrict__ Wr2, const float* __restrict__ Wlin2,
                                const float* __restrict__ b1,  const float* __restrict__ blin1,
                                const float* __restrict__ b2,  const float* __restrict__ blin2) {
    int k = blockIdx.x, n = threadIdx.x;
    float v;
    __nv_bfloat16 *dh, *dl;
    switch (blockIdx.y) {
        case 0:  v = Wl1[k * DD + n];                         dh = g_B1h; dl = g_B1l; break;
        case 1:  v = Wr1[k * DD + n] + Wlin1[k * DD + n];     dh = g_B2h; dl = g_B2l; break;
        case 2:  v = Wl2[k * DD + n];                         dh = g_B3h; dl = g_B3l; break;
        default: v = Wr2[k * DD + n] + Wlin2[k * DD + n];     dh = g_B4h; dl = g_B4l; break;
    }
    __nv_bfloat16 hi = __float2bfloat16(v);
    float lo = v - __bfloat162float(hi);
    dh[n * DD + k] = hi;
    dl[n * DD + k] = __float2bfloat16(lo);
    if (k == 0) {
        if (blockIdx.y == 1) g_b1[n] = b1[n] + blin1[n];
        if (blockIdx.y == 3) g_b2[n] = b2[n] + blin2[n];
    }
}

__global__ void split_x(const float* __restrict__ x) {
    size_t i = (size_t)blockIdx.x * blockDim.x + threadIdx.x;
    if (i >= (size_t)NN * DD) return;
    float v = x[i];
    __nv_bfloat16 hi = __float2bfloat16(v);
    float lo = v - __bfloat162float(hi);
    g_xh[i] = hi;
    g_xl[i] = __float2bfloat16(lo);
}

// ---------------- CSR build --------------------------------------------------
__global__ void scanA() {
    __shared__ int sh[SCAN_B];
    int i = blockIdx.x * SCAN_B + threadIdx.x;
    sh[threadIdx.x] = (i < NN) ? g_deg[i] : 0;
    __syncthreads();
    for (int off = 1; off < SCAN_B; off <<= 1) {
        int t = (threadIdx.x >= off) ? sh[threadIdx.x - off] : 0;
        __syncthreads();
        sh[threadIdx.x] += t;
        __syncthreads();
    }
    if (i < NN) g_scan[i] = sh[threadIdx.x];
    if (threadIdx.x == SCAN_B - 1) g_bsum[blockIdx.x] = sh[SCAN_B - 1];
}

__global__ void scanB() {
    if (threadIdx.x == 0 && blockIdx.x == 0) {
        int run = 0;
        for (int b = 0; b < NBLK; b++) { int t = g_bsum[b]; g_boff[b] = run; run += t; }
    }
}

__global__ void scanC() {
    int i = blockIdx.x * blockDim.x + threadIdx.x;
    if (i < NN) g_rowptr[i] = g_scan[i] - g_deg[i] + g_boff[i / SCAN_B];
    if (i == 0) g_rowptr[NN] = EE;
}

__global__ void fill_csr() {
    int e = blockIdx.x * blockDim.x + threadIdx.x;
    if (e < EE) {
        int d = g_dst[e];
        int pos = g_rowptr[d] + atomicAdd(&g_cursor[d], 1);
        g_csr_src[pos] = g_src[e];
    }
}

// ---------------- mean aggregation: one WARP per dst node -------------------
// INBF=0: gather fp32 feat rows.  INBF=1: gather bf16 hi/lo rows, v = hi+lo.
template <int INBF>
__global__ void __launch_bounds__(256) aggregate_split(
    const float* __restrict__ feat,
    const __nv_bfloat16* __restrict__ fh, const __nv_bfloat16* __restrict__ fl,
    __nv_bfloat16* __restrict__ oh, __nv_bfloat16* __restrict__ ol) {
    int node = blockIdx.x * 8 + (threadIdx.x >> 5);
    int lane = threadIdx.x & 31;
    if (node >= NN) return;
    int start = g_rowptr[node];
    int end   = g_rowptr[node + 1];

    float acc[8] = {0.f, 0.f, 0.f, 0.f, 0.f, 0.f, 0.f, 0.f};

    if (INBF == 0) {
        const float4* f4 = (const float4*)feat;  // 64 float4 per row
        for (int base = start; base < end; base += 32) {
            int cnt = min(32, end - base);
            int my = (base + lane < end) ? g_csr_src[base + lane] : 0;
            int t = 0;
            for (; t + 4 <= cnt; t += 4) {
                int i0 = __shfl_sync(0xffffffffu, my, t);
                int i1 = __shfl_sync(0xffffffffu, my, t + 1);
                int i2 = __shfl_sync(0xffffffffu, my, t + 2);
                int i3 = __shfl_sync(0xffffffffu, my, t + 3);
                const float4* p0 = f4 + (size_t)i0 * 64;
                const float4* p1 = f4 + (size_t)i1 * 64;
                const float4* p2 = f4 + (size_t)i2 * 64;
                const float4* p3 = f4 + (size_t)i3 * 64;
                float4 v00 = p0[lane], v01 = p0[lane + 32];
                float4 v10 = p1[lane], v11 = p1[lane + 32];
                float4 v20 = p2[lane], v21 = p2[lane + 32];
                float4 v30 = p3[lane], v31 = p3[lane + 32];
                acc[0] += (v00.x + v10.x) + (v20.x + v30.x);
                acc[1] += (v00.y + v10.y) + (v20.y + v30.y);
                acc[2] += (v00.z + v10.z) + (v20.z + v30.z);
                acc[3] += (v00.w + v10.w) + (v20.w + v30.w);
                acc[4] += (v01.x + v11.x) + (v21.x + v31.x);
                acc[5] += (v01.y + v11.y) + (v21.y + v31.y);
                acc[6] += (v01.z + v11.z) + (v21.z + v31.z);
                acc[7] += (v01.w + v11.w) + (v21.w + v31.w);
            }
            for (; t < cnt; ++t) {
                int i0 = __shfl_sync(0xffffffffu, my, t);
                const float4* p0 = f4 + (size_t)i0 * 64;
                float4 v00 = p0[lane], v01 = p0[lane + 32];
                acc[0] += v00.x; acc[1] += v00.y; acc[2] += v00.z; acc[3] += v00.w;
                acc[4] += v01.x; acc[5] += v01.y; acc[6] += v01.z; acc[7] += v01.w;
            }
        }
    } else {
        const uint4* H = (const uint4*)fh;   // 32 uint4 (8 bf16 each) per row
        const uint4* L = (const uint4*)fl;
        for (int base = start; base < end; base += 32) {
            int cnt = min(32, end - base);
            int my = (base + lane < end) ? g_csr_src[base + lane] : 0;
            int t = 0;
            for (; t + 2 <= cnt; t += 2) {
                int i0 = __shfl_sync(0xffffffffu, my, t);
                int i1 = __shfl_sync(0xffffffffu, my, t + 1);
                uint4 h0 = H[(size_t)i0 * 32 + lane];
                uint4 l0 = L[(size_t)i0 * 32 + lane];
                uint4 h1 = H[(size_t)i1 * 32 + lane];
                uint4 l1 = L[(size_t)i1 * 32 + lane];
                const uint32_t* hw0 = (const uint32_t*)&h0;
                const uint32_t* lw0 = (const uint32_t*)&l0;
                const uint32_t* hw1 = (const uint32_t*)&h1;
                const uint32_t* lw1 = (const uint32_t*)&l1;
#pragma unroll
                for (int w = 0; w < 4; ++w) {
                    float2 a = __bfloat1622float2(*(const __nv_bfloat162*)&hw0[w]);
                    float2 b = __bfloat1622float2(*(const __nv_bfloat162*)&lw0[w]);
                    float2 c = __bfloat1622float2(*(const __nv_bfloat162*)&hw1[w]);
                    float2 d = __bfloat1622float2(*(const __nv_bfloat162*)&lw1[w]);
                    acc[w * 2 + 0] += (a.x + b.x) + (c.x + d.x);
                    acc[w * 2 + 1] += (a.y + b.y) + (c.y + d.y);
                }
            }
            for (; t < cnt; ++t) {
                int i0 = __shfl_sync(0xffffffffu, my, t);
                uint4 h0 = H[(size_t)i0 * 32 + lane];
                uint4 l0 = L[(size_t)i0 * 32 + lane];
                const uint32_t* hw0 = (const uint32_t*)&h0;
                const uint32_t* lw0 = (const uint32_t*)&l0;
#pragma unroll
                for (int w = 0; w < 4; ++w) {
                    float2 a = __bfloat1622float2(*(const __nv_bfloat162*)&hw0[w]);
                    float2 b = __bfloat1622float2(*(const __nv_bfloat162*)&lw0[w]);
                    acc[w * 2 + 0] += a.x + b.x;
                    acc[w * 2 + 1] += a.y + b.y;
                }
            }
        }
    }

    float scale = (end > start) ? (1.f / (float)(end - start)) : 0.f;
#pragma unroll
    for (int k = 0; k < 8; ++k) acc[k] *= scale;
    size_t rowOff = (size_t)node * DD;

    if (INBF == 0) {
        // lane covers cols lane*4 and 128+lane*4
#pragma unroll
        for (int half = 0; half < 2; ++half) {
            int col = half * 128 + lane * 4;
            __nv_bfloat16 h0 = __float2bfloat16(acc[half * 4 + 0]);
            __nv_bfloat16 h1 = __float2bfloat16(acc[half * 4 + 1]);
            __nv_bfloat16 h2 = __float2bfloat16(acc[half * 4 + 2]);
            __nv_bfloat16 h3 = __float2bfloat16(acc[half * 4 + 3]);
            __nv_bfloat162 hp0; hp0.x = h0; hp0.y = h1;
            __nv_bfloat162 hp1; hp1.x = h2; hp1.y = h3;
            __nv_bfloat162 lp0, lp1;
            lp0.x = __float2bfloat16(acc[half * 4 + 0] - __bfloat162float(h0));
            lp0.y = __float2bfloat16(acc[half * 4 + 1] - __bfloat162float(h1));
            lp1.x = __float2bfloat16(acc[half * 4 + 2] - __bfloat162float(h2));
            lp1.y = __float2bfloat16(acc[half * 4 + 3] - __bfloat162float(h3));
            *(__nv_bfloat162*)&oh[rowOff + col]     = hp0;
            *(__nv_bfloat162*)&oh[rowOff + col + 2] = hp1;
            *(__nv_bfloat162*)&ol[rowOff + col]     = lp0;
            *(__nv_bfloat162*)&ol[rowOff + col + 2] = lp1;
        }
    } else {
        // lane covers cols lane*8..lane*8+7; one uint4 store per array
        uint32_t hw[4], lw[4];
#pragma unroll
        for (int w = 0; w < 4; ++w) {
            __nv_bfloat16 h0 = __float2bfloat16(acc[w * 2 + 0]);
            __nv_bfloat16 h1 = __float2bfloat16(acc[w * 2 + 1]);
            __nv_bfloat162 hp; hp.x = h0; hp.y = h1;
            __nv_bfloat162 lp;
            lp.x = __float2bfloat16(acc[w * 2 + 0] - __bfloat162float(h0));
            lp.y = __float2bfloat16(acc[w * 2 + 1] - __bfloat162float(h1));
            hw[w] = *(uint32_t*)&hp;
            lw[w] = *(uint32_t*)&lp;
        }
        *(uint4*)&oh[rowOff + lane * 8] = make_uint4(hw[0], hw[1], hw[2], hw[3]);
        *(uint4*)&ol[rowOff + lane * 8] = make_uint4(lw[0], lw[1], lw[2], lw[3]);
    }
}

// ---------------- split-bf16 double GEMM via tensor cores -------------------
// C = A1@B1 + A2@B2 + bias; products Ahi@Bhi + Ahi@Blo + Alo@Bhi.
// 24 stages chunk-major over 6 products per K-chunk (A loaded 4x/chunk).
// Fragments loaded via ldmatrix.m8n8.x4 (conflict-free with PADW=36 rows).
// grid (2, rows): the two column-block CTAs per row-block share A via L2.
#define G_BM 128
#define G_BN 128
#define G_BK 64
#define PADW 36                 // words per smem row (32 data + 4 pad)
#define NSTAGES 24              // 4 chunks * 6 products
#define BUF_WORDS (G_BM * PADW)             // 4608 words = 18432 B per buffer
#define BUF_BYTES (BUF_WORDS * 4)
#define GEMM_SMEM_BYTES (4 * BUF_BYTES)     // 2 A + 2 B buffers = 73728

template <int RELU, int SPLIT>
__global__ void __launch_bounds__(256, 2) gemm_mma(
    const __nv_bfloat16* __restrict__ A1h, const __nv_bfloat16* __restrict__ A1l,
    const __nv_bfloat16* __restrict__ A2h, const __nv_bfloat16* __restrict__ A2l,
    const __nv_bfloat16* __restrict__ B1h, const __nv_bfloat16* __restrict__ B1l,
    const __nv_bfloat16* __restrict__ B2h, const __nv_bfloat16* __restrict__ B2l,
    const float* __restrict__ bias,
    float* __restrict__ Cf, __nv_bfloat16* __restrict__ Ch, __nv_bfloat16* __restrict__ Cl,
    int M)
{
    extern __shared__ uint32_t dsm[];
    uint32_t* AsW = dsm;                     // 2 buffers of BUF_WORDS
    uint32_t* BsW = dsm + 2 * BUF_WORDS;

    const int tid  = threadIdx.x;
    const int wid  = tid >> 5;
    const int lane = tid & 31;
    const int grp  = lane >> 2;      // 0..7
    const int tig  = lane & 3;       // 0..3
    const int wm   = (wid & 3) * 32; // warp M offset (4 warps)
    const int wn   = (wid >> 2) * 64;// warp N offset (2 warps)
    const int colBase = blockIdx.x * G_BN;   // grid.x = 2 -> colblocks adjacent
    const int rowBase = blockIdx.y * G_BM;

    const uint32_t aSm = smem_u32(AsW);
    const uint32_t bSm = smem_u32(BsW);
    // ldmatrix per-lane byte offsets (within a buffer), before mi/nj/ks terms:
    //  A: lane L -> row wm + (L&15), word (L>>4)*4
    const uint32_t aLdOff = (uint32_t)((wm + (lane & 15)) * PADW + (lane >> 4) * 4) * 4;
    //  B: lane L -> row wn + ((L>>4)<<3) + (L&7), word ((L>>3)&1)*4
    const uint32_t bLdOff = (uint32_t)((wn + ((lane >> 4) << 3) + (lane & 7)) * PADW
                                       + ((lane >> 3) & 1) * 4) * 4;

    float acc[2][8][4];
#pragma unroll
    for (int mi = 0; mi < 2; mi++)
#pragma unroll
        for (int nj = 0; nj < 8; nj++)
#pragma unroll
            for (int c = 0; c < 4; c++) acc[mi][nj][c] = 0.f;

    // stage decode: j = t%6 product within chunk, c = t/6 chunk
    //  aSel = {A1h,A1h,A1l,A2h,A2h,A2l}, bSel = {B1h,B1l,B1h,B2h,B2l,B2h}
    //  newA at j in {0,2,3,5}; aBuf parity = (#A-loads so far) & 1 = (4c+ai)&1
    auto load_stage = [&](int t) {
        const int j = t % 6, c = t / 6, kk = c * G_BK;
        const int ai = (j > 1) + (j > 2) + (j > 4);           // 0..3
        const int bi = ((j == 1) || (j == 4) ? 1 : 0) + (j >= 3 ? 2 : 0);
        const bool nA = (j != 1) && (j != 4);
        const int aBuf = (c * 4 + ai) & 1;
        const int bBuf = t & 1;
        const __nv_bfloat16* A;
        switch (ai) { case 0: A = A1h; break; case 1: A = A1l; break;
                      case 2: A = A2h; break; default: A = A2l; break; }
        const __nv_bfloat16* B;
        switch (bi) { case 0: B = B1h; break; case 1: B = B1l; break;
                      case 2: B = B2h; break; default: B = B2l; break; }
#pragma unroll
        for (int i = 0; i < 4; i++) {
            int id  = tid + i * 256;
            int row = id >> 3;        // 0..127
            int c16 = id & 7;         // 16B chunk within 128B row
            uint32_t so = (uint32_t)(row * (PADW * 2) + c16 * 8) * 2;  // bytes
            if (nA) {
                int grow = min(rowBase + row, M - 1);
                cp_async16(aSm + aBuf * BUF_BYTES + so,
                           A + (size_t)grow * DD + kk + c16 * 8);
            }
            cp_async16(bSm + bBuf * BUF_BYTES + so,
                       B + (size_t)(colBase + row) * DD + kk + c16 * 8);
        }
    };

    load_stage(0);
    asm volatile("cp.async.commit_group;\n");

    for (int t = 0; t < NSTAGES; ++t) {
        if (t + 1 < NSTAGES) {
            load_stage(t + 1);
            asm volatile("cp.async.commit_group;\n");
            asm volatile("cp.async.wait_group 1;\n");
        } else {
            asm volatile("cp.async.wait_group 0;\n");
        }
        __syncthreads();

        const int j = t % 6, c = t / 6;
        const int ai = (j > 1) + (j > 2) + (j > 4);
        const uint32_t aBase = aSm + (((c * 4 + ai) & 1) ? BUF_BYTES : 0) + aLdOff;
        const uint32_t bBase = bSm + ((t & 1) ? BUF_BYTES : 0) + bLdOff;

#pragma unroll
        for (int ks = 0; ks < 4; ++ks) {
            uint32_t af[2][4], bfr[8][2];
            // A fragments: one ldmatrix.x4 per mi (tiles: rows, rows+8, +4w, +4w rows+8)
#pragma unroll
            for (int mi = 0; mi < 2; ++mi)
                ldmatrix_x4(af[mi][0], af[mi][1], af[mi][2], af[mi][3],
                            aBase + mi * (16 * PADW * 4) + ks * 32);
            // B fragments: one ldmatrix.x4 per nj-pair
#pragma unroll
            for (int p = 0; p < 4; ++p)
                ldmatrix_x4(bfr[2 * p][0], bfr[2 * p][1], bfr[2 * p + 1][0], bfr[2 * p + 1][1],
                            bBase + p * (16 * PADW * 4) + ks * 32);
#pragma unroll
            for (int mi = 0; mi < 2; ++mi)
#pragma unroll
                for (int nj = 0; nj < 8; ++nj)
                    mma_bf16(acc[mi][nj], af[mi], bfr[nj]);
        }
        __syncthreads();
    }

    // epilogue: SPLIT=1 -> write hi/lo bf16 planes only; SPLIT=0 -> fp32 out
#pragma unroll
    for (int mi = 0; mi < 2; ++mi) {
        const int rA = rowBase + wm + mi * 16 + grp;
#pragma unroll
        for (int nj = 0; nj < 8; ++nj) {
            const int col = colBase + wn + nj * 8 + tig * 2;
            const float bb0 = bias[col], bb1 = bias[col + 1];
            float v0 = acc[mi][nj][0] + bb0;
            float v1 = acc[mi][nj][1] + bb1;
            float v2 = acc[mi][nj][2] + bb0;
            float v3 = acc[mi][nj][3] + bb1;
            if (RELU) {
                v0 = fmaxf(v0, 0.f); v1 = fmaxf(v1, 0.f);
                v2 = fmaxf(v2, 0.f); v3 = fmaxf(v3, 0.f);
            }
            if (rA < M) {
                if (SPLIT) {
                    __nv_bfloat16 h0 = __float2bfloat16(v0), h1 = __float2bfloat16(v1);
                    __nv_bfloat162 hp; hp.x = h0; hp.y = h1;
                    __nv_bfloat162 lp;
                    lp.x = __float2bfloat16(v0 - __bfloat162float(h0));
                    lp.y = __float2bfloat16(v1 - __bfloat162float(h1));
                    *(__nv_bfloat162*)&Ch[(size_t)rA * DD + col] = hp;
                    *(__nv_bfloat162*)&Cl[(size_t)rA * DD + col] = lp;
                } else {
                    *(float2*)&Cf[(size_t)rA * DD + col] = make_float2(v0, v1);
                }
            }
            if (rA + 8 < M) {
                if (SPLIT) {
                    __nv_bfloat16 h2 = __float2bfloat16(v2), h3 = __float2bfloat16(v3);
                    __nv_bfloat162 hp; hp.x = h2; hp.y = h3;
                    __nv_bfloat162 lp;
                    lp.x = __float2bfloat16(v2 - __bfloat162float(h2));
                    lp.y = __float2bfloat16(v3 - __bfloat162float(h3));
                    *(__nv_bfloat162*)&Ch[(size_t)(rA + 8) * DD + col] = hp;
                    *(__nv_bfloat162*)&Cl[(size_t)(rA + 8) * DD + col] = lp;
                } else {
                    *(float2*)&Cf[(size_t)(rA + 8) * DD + col] = make_float2(v2, v3);
                }
            }
        }
    }
}

// ---------------- launch -----------------------------------------------------
extern "C" void kernel_launch(void* const* d_in, const int* in_sizes, int n_in,
                              void* d_out, int out_size) {
    const float* x     = (const float*)d_in[0];
    const int*   eidxW = (const int*)d_in[1];   // [2, E], int32 or int64 (auto-detected)
    const float* Wl1   = (const float*)d_in[2];
    const float* Wr1   = (const float*)d_in[3];
    const float* b1    = (const float*)d_in[4];
    const float* Wlin1 = (const float*)d_in[5];
    const float* blin1 = (const float*)d_in[6];
    const float* Wl2   = (const float*)d_in[7];
    const float* Wr2   = (const float*)d_in[8];
    const float* b2    = (const float*)d_in[9];
    const float* Wlin2 = (const float*)d_in[10];
    const float* blin2 = (const float*)d_in[11];
    float* out = (float*)d_out;

    float* b1c; cudaGetSymbolAddress((void**)&b1c, g_b1);
    float* b2c; cudaGetSymbolAddress((void**)&b2c, g_b2);
    __nv_bfloat16 *xh, *xl, *aggh, *aggl, *hh, *hl;
    cudaGetSymbolAddress((void**)&xh, g_xh);
    cudaGetSymbolAddress((void**)&xl, g_xl);
    cudaGetSymbolAddress((void**)&aggh, g_aggh);
    cudaGetSymbolAddress((void**)&aggl, g_aggl);
    cudaGetSymbolAddress((void**)&hh, g_hh);
    cudaGetSymbolAddress((void**)&hl, g_hl);
    __nv_bfloat16 *B1h, *B1l, *B2h, *B2l, *B3h, *B3l, *B4h, *B4l;
    cudaGetSymbolAddress((void**)&B1h, g_B1h);
    cudaGetSymbolAddress((void**)&B1l, g_B1l);
    cudaGetSymbolAddress((void**)&B2h, g_B2h);
    cudaGetSymbolAddress((void**)&B2l, g_B2l);
    cudaGetSymbolAddress((void**)&B3h, g_B3h);
    cudaGetSymbolAddress((void**)&B3l, g_B3l);
    cudaGetSymbolAddress((void**)&B4h, g_B4h);
    cudaGetSymbolAddress((void**)&B4l, g_B4l);

    static cudaStream_t sSide = nullptr;
    static cudaEvent_t evFork = nullptr, evJoin = nullptr;
    if (sSide == nullptr) {
        cudaStreamCreateWithFlags(&sSide, cudaStreamNonBlocking);
        cudaEventCreateWithFlags(&evFork, cudaEventDisableTiming);
        cudaEventCreateWithFlags(&evJoin, cudaEventDisableTiming);
        cudaFuncSetAttribute(gemm_mma<1, 1>, cudaFuncAttributeMaxDynamicSharedMemorySize,
                             GEMM_SMEM_BYTES);
        cudaFuncSetAttribute(gemm_mma<0, 0>, cudaFuncAttributeMaxDynamicSharedMemorySize,
                             GEMM_SMEM_BYTES);
    }

    // fork: weight/feature prep runs on side stream, concurrent with CSR + agg1
    cudaEventRecord(evFork, 0);
    cudaStreamWaitEvent(sSide, evFork, 0);
    transpose_split<<<dim3(DD, 4), DD, 0, sSide>>>(Wl1, Wr1, Wlin1, Wl2, Wr2, Wlin2,
                                                   b1, blin1, b2, blin2);
    split_x<<<(int)(((size_t)NN * DD + 255) / 256), 256, 0, sSide>>>(x);
    cudaEventRecord(evJoin, sSide);

    // main stream: CSR build (extract fused with histogram) then agg1
    zero_counts<<<(NN + 255) / 256, 256>>>();
    extract_hist<<<(EE + 255) / 256, 256>>>(eidxW);
    scanA<<<NBLK, SCAN_B>>>();
    scanB<<<1, 32>>>();
    scanC<<<(NN + 255) / 256, 256>>>();
    fill_csr<<<(EE + 255) / 256, 256>>>();

    dim3 gemmGrid(DD / G_BN, (NN + G_BM - 1) / G_BM);   // (2, 782): colblocks adjacent
    const int aggBlocks = (NN + 7) / 8;

    // layer 1
    aggregate_split<0><<<aggBlocks, 256>>>(x, nullptr, nullptr, aggh, aggl);
    cudaStreamWaitEvent(0, evJoin, 0);   // join prep before GEMM1
    gemm_mma<1, 1><<<gemmGrid, 256, GEMM_SMEM_BYTES>>>(aggh, aggl, xh, xl,
                                                       B1h, B1l, B2h, B2l,
                                                       b1c, nullptr, hh, hl, NN);

    // layer 2
    aggregate_split<1><<<aggBlocks, 256>>>(nullptr, hh, hl, aggh, aggl);
    gemm_mma<0, 0><<<gemmGrid, 256, GEMM_SMEM_BYTES>>>(aggh, aggl, hh, hl,
                                                       B3h, B3l, B4h, B4l,
                                                       b2c, out, nullptr, nullptr, NN);
}

// round 14
// speedup vs baseline: 2.8585x; 1.2405x over previous
#include <cuda_runtime.h>
#include <cuda_fp16.h>
#include <cstdint>

#define NN 100000
#define EE 1600000
#define DD 256
#define SCAN_B 1024
#define NBLK ((NN + SCAN_B - 1) / SCAN_B)   // 98

// ---------------- scratch (device globals; no allocations allowed) ----------
__device__ __half g_xh[(size_t)NN * DD];
__device__ __half g_xl[(size_t)NN * DD];
__device__ __half g_aggh[(size_t)NN * DD];
__device__ __half g_aggl[(size_t)NN * DD];
__device__ __half g_hh[(size_t)NN * DD];
__device__ __half g_hl[(size_t)NN * DD];
__device__ int   g_src[EE];
__device__ int   g_dst[EE];
__device__ int   g_deg[NN];
__device__ int   g_scan[NN];
__device__ int   g_rowptr[NN + 1];
__device__ int   g_cursor[NN];
__device__ int   g_csr_src[EE];
__device__ int   g_bsum[NBLK];
__device__ int   g_boff[NBLK];
__device__ float g_b1[DD];
__device__ float g_b2[DD];
// transposed fp16 B matrices: layout [n][k] (n-major)
__device__ __half g_B1[DD * DD];   // Wl1
__device__ __half g_B2[DD * DD];   // Wr1+Wlin1
__device__ __half g_B3[DD * DD];   // Wl2
__device__ __half g_B4[DD * DD];   // Wr2+Wlin2

// ---------------- PTX helpers ------------------------------------------------
__device__ __forceinline__ void mma_f16(float* d, const uint32_t* a, const uint32_t* b) {
    asm volatile(
        "mma.sync.aligned.m16n8k16.row.col.f32.f16.f16.f32 "
        "{%0,%1,%2,%3}, {%4,%5,%6,%7}, {%8,%9}, {%0,%1,%2,%3};\n"
        : "+f"(d[0]), "+f"(d[1]), "+f"(d[2]), "+f"(d[3])
        : "r"(a[0]), "r"(a[1]), "r"(a[2]), "r"(a[3]), "r"(b[0]), "r"(b[1]));
}

__device__ __forceinline__ void ldmatrix_x4(uint32_t& r0, uint32_t& r1,
                                            uint32_t& r2, uint32_t& r3, uint32_t addr) {
    asm volatile("ldmatrix.sync.aligned.m8n8.x4.shared.b16 {%0,%1,%2,%3}, [%4];"
                 : "=r"(r0), "=r"(r1), "=r"(r2), "=r"(r3) : "r"(addr));
}

__device__ __forceinline__ void cp_async16(uint32_t saddr, const void* gaddr) {
    asm volatile("cp.async.cg.shared.global [%0], [%1], 16;\n" :: "r"(saddr), "l"(gaddr));
}

__device__ __forceinline__ uint32_t smem_u32(const void* p) {
    return (uint32_t)__cvta_generic_to_shared(p);
}

// ---------------- counters init ----------------------------------------------
__global__ void zero_counts() {
    int i = blockIdx.x * blockDim.x + threadIdx.x;
    if (i < NN) { g_deg[i] = 0; g_cursor[i] = 0; }
}

// ---------------- edge extraction + histogram (fused) ------------------------
__global__ void extract_hist(const int* __restrict__ w) {
    __shared__ int nz;
    if (threadIdx.x == 0) nz = 0;
    __syncthreads();
    for (int i = threadIdx.x; i < 1024; i += blockDim.x)
        if (w[2 * i + 1] != 0) { nz = 1; break; }
    __syncthreads();
    const int is64 = (nz == 0);

    int e = blockIdx.x * blockDim.x + threadIdx.x;
    if (e >= EE) return;
    int s, d;
    if (is64) {
        s = w[2 * (size_t)e];
        d = w[2 * ((size_t)EE + e)];
    } else {
        s = w[e];
        d = w[EE + e];
    }
    s = min(max(s, 0), NN - 1);
    d = min(max(d, 0), NN - 1);
    g_src[e] = s;
    g_dst[e] = d;
    atomicAdd(&g_deg[d], 1);
}

// ---------------- prep: combine + transpose to fp16 (one kernel) ------------
__global__ void transpose_f16(const float* __restrict__ Wl1,
                              const float* __restrict__ Wr1, const float* __restrict__ Wlin1,
                              const float* __restrict__ Wl2,
                              const float* __restrict__ Wr2, const float* __restrict__ Wlin2,
                              const float* __restrict__ b1,  const float* __restrict__ blin1,
                              const float* __restrict__ b2,  const float* __restrict__ blin2) {
    int k = blockIdx.x, n = threadIdx.x;
    float v;
    __half* dst;
    switch (blockIdx.y) {
        case 0:  v = Wl1[k * DD + n];                      dst = g_B1; break;
        case 1:  v = Wr1[k * DD + n] + Wlin1[k * DD + n];  dst = g_B2; break;
        case 2:  v = Wl2[k * DD + n];                      dst = g_B3; break;
        default: v = Wr2[k * DD + n] + Wlin2[k * DD + n];  dst = g_B4; break;
    }
    dst[n * DD + k] = __float2half_rn(v);
    if (k == 0) {
        if (blockIdx.y == 1) g_b1[n] = b1[n] + blin1[n];
        if (blockIdx.y == 3) g_b2[n] = b2[n] + blin2[n];
    }
}

__global__ void split_x(const float* __restrict__ x) {
    size_t i = (size_t)blockIdx.x * blockDim.x + threadIdx.x;
    if (i >= (size_t)NN * DD) return;
    float v = x[i];
    __half hi = __float2half_rn(v);
    g_xh[i] = hi;
    g_xl[i] = __float2half_rn(v - __half2float(hi));
}

// ---------------- CSR build --------------------------------------------------
__global__ void scanA() {
    __shared__ int sh[SCAN_B];
    int i = blockIdx.x * SCAN_B + threadIdx.x;
    sh[threadIdx.x] = (i < NN) ? g_deg[i] : 0;
    __syncthreads();
    for (int off = 1; off < SCAN_B; off <<= 1) {
        int t = (threadIdx.x >= off) ? sh[threadIdx.x - off] : 0;
        __syncthreads();
        sh[threadIdx.x] += t;
        __syncthreads();
    }
    if (i < NN) g_scan[i] = sh[threadIdx.x];
    if (threadIdx.x == SCAN_B - 1) g_bsum[blockIdx.x] = sh[SCAN_B - 1];
}

__global__ void scanB() {
    if (threadIdx.x == 0 && blockIdx.x == 0) {
        int run = 0;
        for (int b = 0; b < NBLK; b++) { int t = g_bsum[b]; g_boff[b] = run; run += t; }
    }
}

__global__ void scanC() {
    int i = blockIdx.x * blockDim.x + threadIdx.x;
    if (i < NN) g_rowptr[i] = g_scan[i] - g_deg[i] + g_boff[i / SCAN_B];
    if (i == 0) g_rowptr[NN] = EE;
}

__global__ void fill_csr() {
    int e = blockIdx.x * blockDim.x + threadIdx.x;
    if (e < EE) {
        int d = g_dst[e];
        int pos = g_rowptr[d] + atomicAdd(&g_cursor[d], 1);
        g_csr_src[pos] = g_src[e];
    }
}

// ---------------- mean aggregation: one WARP per dst node -------------------
// INBF=0: gather fp32 feat rows.  INBF=1: gather fp16 hi/lo rows, v = hi+lo.
template <int INBF>
__global__ void __launch_bounds__(256) aggregate_split(
    const float* __restrict__ feat,
    const __half* __restrict__ fh, const __half* __restrict__ fl,
    __half* __restrict__ oh, __half* __restrict__ ol) {
    int node = blockIdx.x * 8 + (threadIdx.x >> 5);
    int lane = threadIdx.x & 31;
    if (node >= NN) return;
    int start = g_rowptr[node];
    int end   = g_rowptr[node + 1];

    float acc[8] = {0.f, 0.f, 0.f, 0.f, 0.f, 0.f, 0.f, 0.f};

    if (INBF == 0) {
        const float4* f4 = (const float4*)feat;  // 64 float4 per row
        for (int base = start; base < end; base += 32) {
            int cnt = min(32, end - base);
            int my = (base + lane < end) ? g_csr_src[base + lane] : 0;
            int t = 0;
            for (; t + 4 <= cnt; t += 4) {
                int i0 = __shfl_sync(0xffffffffu, my, t);
                int i1 = __shfl_sync(0xffffffffu, my, t + 1);
                int i2 = __shfl_sync(0xffffffffu, my, t + 2);
                int i3 = __shfl_sync(0xffffffffu, my, t + 3);
                const float4* p0 = f4 + (size_t)i0 * 64;
                const float4* p1 = f4 + (size_t)i1 * 64;
                const float4* p2 = f4 + (size_t)i2 * 64;
                const float4* p3 = f4 + (size_t)i3 * 64;
                float4 v00 = p0[lane], v01 = p0[lane + 32];
                float4 v10 = p1[lane], v11 = p1[lane + 32];
                float4 v20 = p2[lane], v21 = p2[lane + 32];
                float4 v30 = p3[lane], v31 = p3[lane + 32];
                acc[0] += (v00.x + v10.x) + (v20.x + v30.x);
                acc[1] += (v00.y + v10.y) + (v20.y + v30.y);
                acc[2] += (v00.z + v10.z) + (v20.z + v30.z);
                acc[3] += (v00.w + v10.w) + (v20.w + v30.w);
                acc[4] += (v01.x + v11.x) + (v21.x + v31.x);
                acc[5] += (v01.y + v11.y) + (v21.y + v31.y);
                acc[6] += (v01.z + v11.z) + (v21.z + v31.z);
                acc[7] += (v01.w + v11.w) + (v21.w + v31.w);
            }
            for (; t < cnt; ++t) {
                int i0 = __shfl_sync(0xffffffffu, my, t);
                const float4* p0 = f4 + (size_t)i0 * 64;
                float4 v00 = p0[lane], v01 = p0[lane + 32];
                acc[0] += v00.x; acc[1] += v00.y; acc[2] += v00.z; acc[3] += v00.w;
                acc[4] += v01.x; acc[5] += v01.y; acc[6] += v01.z; acc[7] += v01.w;
            }
        }
    } else {
        const uint4* H = (const uint4*)fh;   // 32 uint4 (8 fp16 each) per row
        const uint4* L = (const uint4*)fl;
        for (int base = start; base < end; base += 32) {
            int cnt = min(32, end - base);
            int my = (base + lane < end) ? g_csr_src[base + lane] : 0;
            int t = 0;
            for (; t + 2 <= cnt; t += 2) {
                int i0 = __shfl_sync(0xffffffffu, my, t);
                int i1 = __shfl_sync(0xffffffffu, my, t + 1);
                uint4 h0 = H[(size_t)i0 * 32 + lane];
                uint4 l0 = L[(size_t)i0 * 32 + lane];
                uint4 h1 = H[(size_t)i1 * 32 + lane];
                uint4 l1 = L[(size_t)i1 * 32 + lane];
                const uint32_t* hw0 = (const uint32_t*)&h0;
                const uint32_t* lw0 = (const uint32_t*)&l0;
                const uint32_t* hw1 = (const uint32_t*)&h1;
                const uint32_t* lw1 = (const uint32_t*)&l1;
#pragma unroll
                for (int w = 0; w < 4; ++w) {
                    float2 a = __half22float2(*(const __half2*)&hw0[w]);
                    float2 b = __half22float2(*(const __half2*)&lw0[w]);
                    float2 c = __half22float2(*(const __half2*)&hw1[w]);
                    float2 d = __half22float2(*(const __half2*)&lw1[w]);
                    acc[w * 2 + 0] += (a.x + b.x) + (c.x + d.x);
                    acc[w * 2 + 1] += (a.y + b.y) + (c.y + d.y);
                }
            }
            for (; t < cnt; ++t) {
                int i0 = __shfl_sync(0xffffffffu, my, t);
                uint4 h0 = H[(size_t)i0 * 32 + lane];
                uint4 l0 = L[(size_t)i0 * 32 + lane];
                const uint32_t* hw0 = (const uint32_t*)&h0;
                const uint32_t* lw0 = (const uint32_t*)&l0;
#pragma unroll
                for (int w = 0; w < 4; ++w) {
                    float2 a = __half22float2(*(const __half2*)&hw0[w]);
                    float2 b = __half22float2(*(const __half2*)&lw0[w]);
                    acc[w * 2 + 0] += a.x + b.x;
                    acc[w * 2 + 1] += a.y + b.y;
                }
            }
        }
    }

    float scale = (end > start) ? (1.f / (float)(end - start)) : 0.f;
#pragma unroll
    for (int k = 0; k < 8; ++k) acc[k] *= scale;
    size_t rowOff = (size_t)node * DD;

    if (INBF == 0) {
#pragma unroll
        for (int half = 0; half < 2; ++half) {
            int col = half * 128 + lane * 4;
            __half h0 = __float2half_rn(acc[half * 4 + 0]);
            __half h1 = __float2half_rn(acc[half * 4 + 1]);
            __half h2 = __float2half_rn(acc[half * 4 + 2]);
            __half h3 = __float2half_rn(acc[half * 4 + 3]);
            __half2 hp0 = __halves2half2(h0, h1);
            __half2 hp1 = __halves2half2(h2, h3);
            __half2 lp0 = __halves2half2(
                __float2half_rn(acc[half * 4 + 0] - __half2float(h0)),
                __float2half_rn(acc[half * 4 + 1] - __half2float(h1)));
            __half2 lp1 = __halves2half2(
                __float2half_rn(acc[half * 4 + 2] - __half2float(h2)),
                __float2half_rn(acc[half * 4 + 3] - __half2float(h3)));
            *(__half2*)&oh[rowOff + col]     = hp0;
            *(__half2*)&oh[rowOff + col + 2] = hp1;
            *(__half2*)&ol[rowOff + col]     = lp0;
            *(__half2*)&ol[rowOff + col + 2] = lp1;
        }
    } else {
        uint32_t hw[4], lw[4];
#pragma unroll
        for (int w = 0; w < 4; ++w) {
            __half h0 = __float2half_rn(acc[w * 2 + 0]);
            __half h1 = __float2half_rn(acc[w * 2 + 1]);
            __half2 hp = __halves2half2(h0, h1);
            __half2 lp = __halves2half2(
                __float2half_rn(acc[w * 2 + 0] - __half2float(h0)),
                __float2half_rn(acc[w * 2 + 1] - __half2float(h1)));
            hw[w] = *(uint32_t*)&hp;
            lw[w] = *(uint32_t*)&lp;
        }
        *(uint4*)&oh[rowOff + lane * 8] = make_uint4(hw[0], hw[1], hw[2], hw[3]);
        *(uint4*)&ol[rowOff + lane * 8] = make_uint4(lw[0], lw[1], lw[2], lw[3]);
    }
}

// ---------------- fp16 split-A double GEMM via tensor cores -----------------
// C = A1@B1 + A2@B2 + bias.  A split fp16 hi/lo (A err ~2^-22); B single fp16
// (rounding ~2^-11 RMS dominates rel_err ~2-4e-4, under 1e-3 with margin).
// Products per K-chunk: A1h@B1, A1l@B1, A2h@B2, A2l@B2 -> 16 stages.
// Fragments via ldmatrix.m8n8.x4; PADW=36 rows conflict-free.
// grid (2, rows): the two column-block CTAs per row-block share A via L2.
#define G_BM 128
#define G_BN 128
#define G_BK 64
#define PADW 36                 // words per smem row (32 data + 4 pad)
#define NSTAGES 16              // 4 chunks * 4 products
#define BUF_WORDS (G_BM * PADW)             // 4608 words = 18432 B per buffer
#define BUF_BYTES (BUF_WORDS * 4)
#define GEMM_SMEM_BYTES (4 * BUF_BYTES)     // 2 A + 2 B buffers = 73728

template <int RELU, int SPLIT>
__global__ void __launch_bounds__(256, 2) gemm_mma(
    const __half* __restrict__ A1h, const __half* __restrict__ A1l,
    const __half* __restrict__ A2h, const __half* __restrict__ A2l,
    const __half* __restrict__ B1,  const __half* __restrict__ B2,
    const float* __restrict__ bias,
    float* __restrict__ Cf, __half* __restrict__ Ch, __half* __restrict__ Cl,
    int M)
{
    extern __shared__ uint32_t dsm[];
    uint32_t* AsW = dsm;                     // 2 buffers of BUF_WORDS
    uint32_t* BsW = dsm + 2 * BUF_WORDS;

    const int tid  = threadIdx.x;
    const int wid  = tid >> 5;
    const int lane = tid & 31;
    const int grp  = lane >> 2;      // 0..7
    const int tig  = lane & 3;       // 0..3
    const int wm   = (wid & 3) * 32; // warp M offset (4 warps)
    const int wn   = (wid >> 2) * 64;// warp N offset (2 warps)
    const int colBase = blockIdx.x * G_BN;   // grid.x = 2 -> colblocks adjacent
    const int rowBase = blockIdx.y * G_BM;

    const uint32_t aSm = smem_u32(AsW);
    const uint32_t bSm = smem_u32(BsW);
    const uint32_t aLdOff = (uint32_t)((wm + (lane & 15)) * PADW + (lane >> 4) * 4) * 4;
    const uint32_t bLdOff = (uint32_t)((wn + ((lane >> 4) << 3) + (lane & 7)) * PADW
                                       + ((lane >> 3) & 1) * 4) * 4;

    float acc[2][8][4];
#pragma unroll
    for (int mi = 0; mi < 2; mi++)
#pragma unroll
        for (int nj = 0; nj < 8; nj++)
#pragma unroll
            for (int c = 0; c < 4; c++) acc[mi][nj][c] = 0.f;

    // stage decode: j = t&3 product within chunk, c = t>>2 chunk
    //  A plane = {A1h, A1l, A2h, A2l}[j], loaded every stage, aBuf = t&1
    //  B plane = {B1, B2}[j>>1], loaded when (j&1)==0, bBuf = (2c + (j>>1))&1
    auto load_stage = [&](int t) {
        const int j = t & 3, c = t >> 2, kk = c * G_BK;
        const __half* A;
        switch (j) { case 0: A = A1h; break; case 1: A = A1l; break;
                     case 2: A = A2h; break; default: A = A2l; break; }
        const bool nB = (j & 1) == 0;
        const int bi = j >> 1;
        const __half* B = bi ? B2 : B1;
        const int aBuf = t & 1;
        const int bBuf = (2 * c + bi) & 1;
#pragma unroll
        for (int i = 0; i < 4; i++) {
            int id  = tid + i * 256;
            int row = id >> 3;        // 0..127
            int c16 = id & 7;         // 16B chunk within 128B row
            uint32_t so = (uint32_t)(row * (PADW * 2) + c16 * 8) * 2;  // bytes
            int grow = min(rowBase + row, M - 1);
            cp_async16(aSm + aBuf * BUF_BYTES + so,
                       A + (size_t)grow * DD + kk + c16 * 8);
            if (nB)
                cp_async16(bSm + bBuf * BUF_BYTES + so,
                           B + (size_t)(colBase + row) * DD + kk + c16 * 8);
        }
    };

    load_stage(0);
    asm volatile("cp.async.commit_group;\n");

    for (int t = 0; t < NSTAGES; ++t) {
        if (t + 1 < NSTAGES) {
            load_stage(t + 1);
            asm volatile("cp.async.commit_group;\n");
            asm volatile("cp.async.wait_group 1;\n");
        } else {
            asm volatile("cp.async.wait_group 0;\n");
        }
        __syncthreads();

        const int j = t & 3, c = t >> 2;
        const uint32_t aBase = aSm + ((t & 1) ? BUF_BYTES : 0) + aLdOff;
        const uint32_t bBase = bSm + (((2 * c + (j >> 1)) & 1) ? BUF_BYTES : 0) + bLdOff;

#pragma unroll
        for (int ks = 0; ks < 4; ++ks) {
            uint32_t af[2][4], bfr[8][2];
#pragma unroll
            for (int mi = 0; mi < 2; ++mi)
                ldmatrix_x4(af[mi][0], af[mi][1], af[mi][2], af[mi][3],
                            aBase + mi * (16 * PADW * 4) + ks * 32);
#pragma unroll
            for (int p = 0; p < 4; ++p)
                ldmatrix_x4(bfr[2 * p][0], bfr[2 * p][1], bfr[2 * p + 1][0], bfr[2 * p + 1][1],
                            bBase + p * (16 * PADW * 4) + ks * 32);
#pragma unroll
            for (int mi = 0; mi < 2; ++mi)
#pragma unroll
                for (int nj = 0; nj < 8; ++nj)
                    mma_f16(acc[mi][nj], af[mi], bfr[nj]);
        }
        __syncthreads();
    }

    // epilogue: SPLIT=1 -> write fp16 hi/lo planes; SPLIT=0 -> fp32 out
#pragma unroll
    for (int mi = 0; mi < 2; ++mi) {
        const int rA = rowBase + wm + mi * 16 + grp;
#pragma unroll
        for (int nj = 0; nj < 8; ++nj) {
            const int col = colBase + wn + nj * 8 + tig * 2;
            const float bb0 = bias[col], bb1 = bias[col + 1];
            float v0 = acc[mi][nj][0] + bb0;
            float v1 = acc[mi][nj][1] + bb1;
            float v2 = acc[mi][nj][2] + bb0;
            float v3 = acc[mi][nj][3] + bb1;
            if (RELU) {
                v0 = fmaxf(v0, 0.f); v1 = fmaxf(v1, 0.f);
                v2 = fmaxf(v2, 0.f); v3 = fmaxf(v3, 0.f);
            }
            if (rA < M) {
                if (SPLIT) {
                    __half h0 = __float2half_rn(v0), h1 = __float2half_rn(v1);
                    __half2 hp = __halves2half2(h0, h1);
                    __half2 lp = __halves2half2(
                        __float2half_rn(v0 - __half2float(h0)),
                        __float2half_rn(v1 - __half2float(h1)));
                    *(__half2*)&Ch[(size_t)rA * DD + col] = hp;
                    *(__half2*)&Cl[(size_t)rA * DD + col] = lp;
                } else {
                    *(float2*)&Cf[(size_t)rA * DD + col] = make_float2(v0, v1);
                }
            }
            if (rA + 8 < M) {
                if (SPLIT) {
                    __half h2 = __float2half_rn(v2), h3 = __float2half_rn(v3);
                    __half2 hp = __halves2half2(h2, h3);
                    __half2 lp = __halves2half2(
                        __float2half_rn(v2 - __half2float(h2)),
                        __float2half_rn(v3 - __half2float(h3)));
                    *(__half2*)&Ch[(size_t)(rA + 8) * DD + col] = hp;
                    *(__half2*)&Cl[(size_t)(rA + 8) * DD + col] = lp;
                } else {
                    *(float2*)&Cf[(size_t)(rA + 8) * DD + col] = make_float2(v2, v3);
                }
            }
        }
    }
}

// ---------------- launch -----------------------------------------------------
extern "C" void kernel_launch(void* const* d_in, const int* in_sizes, int n_in,
                              void* d_out, int out_size) {
    const float* x     = (const float*)d_in[0];
    const int*   eidxW = (const int*)d_in[1];   // [2, E], int32 or int64 (auto-detected)
    const float* Wl1   = (const float*)d_in[2];
    const float* Wr1   = (const float*)d_in[3];
    const float* b1    = (const float*)d_in[4];
    const float* Wlin1 = (const float*)d_in[5];
    const float* blin1 = (const float*)d_in[6];
    const float* Wl2   = (const float*)d_in[7];
    const float* Wr2   = (const float*)d_in[8];
    const float* b2    = (const float*)d_in[9];
    const float* Wlin2 = (const float*)d_in[10];
    const float* blin2 = (const float*)d_in[11];
    float* out = (float*)d_out;

    float* b1c; cudaGetSymbolAddress((void**)&b1c, g_b1);
    float* b2c; cudaGetSymbolAddress((void**)&b2c, g_b2);
    __half *xh, *xl, *aggh, *aggl, *hh, *hl;
    cudaGetSymbolAddress((void**)&xh, g_xh);
    cudaGetSymbolAddress((void**)&xl, g_xl);
    cudaGetSymbolAddress((void**)&aggh, g_aggh);
    cudaGetSymbolAddress((void**)&aggl, g_aggl);
    cudaGetSymbolAddress((void**)&hh, g_hh);
    cudaGetSymbolAddress((void**)&hl, g_hl);
    __half *B1, *B2, *B3, *B4;
    cudaGetSymbolAddress((void**)&B1, g_B1);
    cudaGetSymbolAddress((void**)&B2, g_B2);
    cudaGetSymbolAddress((void**)&B3, g_B3);
    cudaGetSymbolAddress((void**)&B4, g_B4);

    static cudaStream_t sSide = nullptr;
    static cudaEvent_t evFork = nullptr, evJoin = nullptr;
    if (sSide == nullptr) {
        cudaStreamCreateWithFlags(&sSide, cudaStreamNonBlocking);
        cudaEventCreateWithFlags(&evFork, cudaEventDisableTiming);
        cudaEventCreateWithFlags(&evJoin, cudaEventDisableTiming);
        cudaFuncSetAttribute(gemm_mma<1, 1>, cudaFuncAttributeMaxDynamicSharedMemorySize,
                             GEMM_SMEM_BYTES);
        cudaFuncSetAttribute(gemm_mma<0, 0>, cudaFuncAttributeMaxDynamicSharedMemorySize,
                             GEMM_SMEM_BYTES);
    }

    // fork: weight/feature prep on side stream, concurrent with CSR + agg1
    cudaEventRecord(evFork, 0);
    cudaStreamWaitEvent(sSide, evFork, 0);
    transpose_f16<<<dim3(DD, 4), DD, 0, sSide>>>(Wl1, Wr1, Wlin1, Wl2, Wr2, Wlin2,
                                                 b1, blin1, b2, blin2);
    split_x<<<(int)(((size_t)NN * DD + 255) / 256), 256, 0, sSide>>>(x);
    cudaEventRecord(evJoin, sSide);

    // main stream: CSR build (extract fused with histogram)
    zero_counts<<<(NN + 255) / 256, 256>>>();
    extract_hist<<<(EE + 255) / 256, 256>>>(eidxW);
    scanA<<<NBLK, SCAN_B>>>();
    scanB<<<1, 32>>>();
    scanC<<<(NN + 255) / 256, 256>>>();
    fill_csr<<<(EE + 255) / 256, 256>>>();

    dim3 gemmGrid(DD / G_BN, (NN + G_BM - 1) / G_BM);   // (2, 782): colblocks adjacent
    const int aggBlocks = (NN + 7) / 8;

    // layer 1
    aggregate_split<0><<<aggBlocks, 256>>>(x, nullptr, nullptr, aggh, aggl);
    cudaStreamWaitEvent(0, evJoin, 0);   // join prep before GEMM1
    gemm_mma<1, 1><<<gemmGrid, 256, GEMM_SMEM_BYTES>>>(aggh, aggl, xh, xl,
                                                       B1, B2,
                                                       b1c, nullptr, hh, hl, NN);

    // layer 2
    aggregate_split<1><<<aggBlocks, 256>>>(nullptr, hh, hl, aggh, aggl);
    gemm_mma<0, 0><<<gemmGrid, 256, GEMM_SMEM_BYTES>>>(aggh, aggl, hh, hl,
                                                       B3, B4,
                                                       b2c, out, nullptr, nullptr, NN);
}